// round 14
// baseline (speedup 1.0000x reference)
#include <cuda_runtime.h>
#include <cuda_bf16.h>
#include <math.h>
#include <stdint.h>

// ---------------- problem constants ----------------
#define B        128
#define TV       256
#define TS       40
#define VIN      1024
#define VHID     512
#define SIN      300
#define SHID     256
#define NCAT     2624
#define NFEAT    1024
#define LCROSS   512
#define NLOC     64

#define VF_ELEMS   ((size_t)B*TV*2*VHID)
#define SF_ELEMS   ((size_t)B*2*SHID)

// ---------------- scratch (__device__ globals) ----------------
__device__ float g_xp_v[(size_t)B*TV*3072];
__device__ float g_xp_s[(size_t)B*TS*1536];
__device__ float g_h_v[2*B*VHID];
__device__ float g_h_s[2*B*SHID];
__device__ uint32_t g_hpk_hi_v[2*B*VHID/2], g_hpk_lo_v[2*B*VHID/2];
__device__ uint32_t g_hpk_hi_s[2*B*SHID/2], g_hpk_lo_s[2*B*SHID/2];
__device__ float g_part_v[8*2*B*1536];
__device__ float g_part_s[4*2*B*768];
__device__ float g_words[(size_t)B*TS*2*SHID];
__device__ float g_lmean[B*1024];
__device__ float g_rmean[B*1024];
__device__ float g_cat[B*NCAT];
__device__ float g_sproj[B*LCROSS];
__device__ int   g_perm_v[B], g_lenp_v[B];
__device__ int   g_perm_s[B], g_lenp_s[B];
__device__ int   g_cnt_v[TV], g_cnt_s[TS];
__device__ int   g_ridx_v[B*TV], g_ridx_s[B*TS];
__device__ int   g_nv[2];
__device__ unsigned g_bar[4];

// ---------------- init ----------------
__global__ void sort_init_kernel(const int* __restrict__ v_len,
                                 const int* __restrict__ lens,
                                 int* pv, int* lv, int* ps, int* ls,
                                 int* cv, int* cs,
                                 int* ridxv, int* ridxs, int* nv,
                                 unsigned* bar)
{
    int i = threadIdx.x;
    if (i < 4) bar[i] = 0u;

    for (int e = i; e < B*TV; e += 128) ridxv[e] = -1;
    for (int e = i; e < B*TS; e += 128) ridxs[e] = -1;
    __syncthreads();

    int a = v_len[i], rank = 0;
    for (int j = 0; j < B; j++) {
        int c = v_len[j];
        rank += (c > a) || (c == a && j < i);
    }
    pv[rank] = i; lv[rank] = a;
    a = lens[i]; rank = 0;
    for (int j = 0; j < B; j++) {
        int c = lens[j];
        rank += (c > a) || (c == a && j < i);
    }
    ps[rank] = i; ls[rank] = a;

    for (int t = i; t < TV; t += 128) {
        int c = 0;
        for (int j = 0; j < B; j++) c += (v_len[j] > t);
        cv[t] = c;
    }
    for (int t = i; t < TS; t += 128) {
        int c = 0;
        for (int j = 0; j < B; j++) c += (lens[j] > t);
        cs[t] = c;
    }

    int offv = 0, offs = 0;
    for (int j = 0; j < i; j++) { offv += v_len[j]; offs += lens[j]; }
    int lv_i = v_len[i], ls_i = lens[i];
    for (int t = 0; t < lv_i; t++) ridxv[offv + t] = i * TV + t;
    for (int t = 0; t < ls_i; t++) ridxs[offs + t] = i * TS + t;
    if (i == B - 1) {
        nv[0] = offv + lv_i;
        nv[1] = offs + ls_i;
    }
}

__global__ void zero_h_kernel(float* hv, float* hs,
                              uint32_t* phv, uint32_t* plv,
                              uint32_t* phs, uint32_t* pls) {
    int i = blockIdx.x * blockDim.x + threadIdx.x;
    if (i < 2*B*VHID) hv[i] = 0.f;
    if (i < 2*B*SHID) hs[i] = 0.f;
    if (i < 2*B*VHID/2) { phv[i] = 0u; plv[i] = 0u; }
    if (i < 2*B*SHID/2) { phs[i] = 0u; pls[i] = 0u; }
}

__global__ void zero_out_kernel(float4* p, int n4) {
    int i = blockIdx.x * blockDim.x + threadIdx.x;
    if (i < n4) p[i] = make_float4(0.f, 0.f, 0.f, 0.f);
}

// ---------------- numeric helpers ----------------
__device__ __forceinline__ void mma_bf16(float* d, const uint32_t* a, const uint32_t* b) {
    asm volatile(
        "mma.sync.aligned.m16n8k16.row.col.f32.bf16.bf16.f32 "
        "{%0,%1,%2,%3}, {%4,%5,%6,%7}, {%8,%9}, {%0,%1,%2,%3};"
        : "+f"(d[0]), "+f"(d[1]), "+f"(d[2]), "+f"(d[3])
        : "r"(a[0]), "r"(a[1]), "r"(a[2]), "r"(a[3]), "r"(b[0]), "r"(b[1]));
}
__device__ __forceinline__ void ldsm_x4(uint32_t* r, uint32_t saddr) {
    asm volatile("ldmatrix.sync.aligned.m8n8.x4.shared.b16 {%0,%1,%2,%3}, [%4];"
                 : "=r"(r[0]), "=r"(r[1]), "=r"(r[2]), "=r"(r[3]) : "r"(saddr));
}
__device__ __forceinline__ uint32_t bfpack(__nv_bfloat16 lo, __nv_bfloat16 hi) {
    uint32_t l = __bfloat16_as_ushort(lo);
    uint32_t h = __bfloat16_as_ushort(hi);
    return l | (h << 16);
}
__device__ __forceinline__ void bfsplit2(float x0, float x1,
                                         uint32_t& hi, uint32_t& lo) {
    __nv_bfloat16 h0 = __float2bfloat16_rn(x0);
    __nv_bfloat16 h1 = __float2bfloat16_rn(x1);
    hi = bfpack(h0, h1);
    __nv_bfloat16 l0 = __float2bfloat16_rn(x0 - __bfloat162float(h0));
    __nv_bfloat16 l1 = __float2bfloat16_rn(x1 - __bfloat162float(h1));
    lo = bfpack(l0, l1);
}
__device__ __forceinline__ float4 ld_guard4(const float* p, int kg, int K) {
    if (kg + 4 <= K) return *(const float4*)p;
    float4 v;
    v.x = (kg     < K) ? p[0] : 0.f;
    v.y = (kg + 1 < K) ? p[1] : 0.f;
    v.z = (kg + 2 < K) ? p[2] : 0.f;
    v.w = (kg + 3 < K) ? p[3] : 0.f;
    return v;
}
__device__ __forceinline__ float fast_sigmoid(float x) {
    return __fdividef(1.f, 1.f + __expf(-x));
}
__device__ __forceinline__ float fast_tanh(float x) {
    return __fdividef(2.f, 1.f + __expf(-2.f * x)) - 1.f;
}

// ---------------- 3xBF16 tensor-core GEMM, row-compacted ----------
#define GEMM_SMEM (4 * 2 * 128 * 12 * 4)     // 49152 B
__global__ __launch_bounds__(256, 2) void gemm_bf16x3(
    const float* __restrict__ A, const float* __restrict__ W,
    const float* __restrict__ bias, float* __restrict__ C,
    const int* __restrict__ ridx, const int* __restrict__ nvp,
    int N, int K)
{
    extern __shared__ uint32_t dsm[];
    const int AH = 0, AL = 2*128*12, WH = 2*AL, WL = 3*AL;
    __shared__ int sridx[128];

    const int n0 = blockIdx.x * 128;
    const int m0 = blockIdx.y * 128;
    const int tid = threadIdx.x;

    const int nv = *nvp;
    if (m0 >= nv) return;

    if (tid < 128) sridx[tid] = ridx[m0 + tid];
    __syncthreads();

    const int wid  = tid / 32, lane = tid % 32;
    const int wm   = (wid / 4) * 64;
    const int wn   = (wid % 4) * 32;
    const int gid  = lane >> 2, tig = lane & 3;
    const int quad = lane >> 3, lrow = lane & 7;
    const int arow = ((quad & 1) << 3) + lrow;
    const int ak2  = (quad >> 1) * 4;
    const int wrow = ((quad >> 1) << 3) + lrow;
    const int wk2  = (quad & 1) * 4;
    const uint32_t sbase = (uint32_t)__cvta_generic_to_shared(dsm);
    const int niter = (K + 15) >> 4;

    const int c0r = tid >> 2,          c0k = (tid & 3) * 4;
    const int c1r = (tid + 256) >> 2,  c1k = ((tid + 256) & 3) * 4;
    const int rm0 = sridx[c0r] < 0 ? 0 : sridx[c0r];
    const int rm1 = sridx[c1r] < 0 ? 0 : sridx[c1r];

    float acc[4][4][4];
#pragma unroll
    for (int i = 0; i < 4; i++)
#pragma unroll
        for (int j = 0; j < 4; j++)
#pragma unroll
            for (int c = 0; c < 4; c++) acc[i][j][c] = 0.f;

    float4 ra0, ra1, rw0, rw1;
    ra0 = ld_guard4(A + (size_t)rm0 * K + c0k, c0k, K);
    ra1 = ld_guard4(A + (size_t)rm1 * K + c1k, c1k, K);
    rw0 = ld_guard4(W + (size_t)(n0 + c0r) * K + c0k, c0k, K);
    rw1 = ld_guard4(W + (size_t)(n0 + c1r) * K + c1k, c1k, K);

    for (int kt = 0; kt < niter; kt++) {
        const int buf = kt & 1;
        const int bo = buf * 128;
        {
            uint32_t h0, l0, h1, l1;
            int k2 = c0k >> 1;
            int r0i = (bo + c0r) * 12, r1i = (bo + c1r) * 12;
            bfsplit2(ra0.x, ra0.y, h0, l0); bfsplit2(ra0.z, ra0.w, h1, l1);
            *(uint2*)&dsm[AH + r0i + k2] = make_uint2(h0, h1);
            *(uint2*)&dsm[AL + r0i + k2] = make_uint2(l0, l1);
            bfsplit2(rw0.x, rw0.y, h0, l0); bfsplit2(rw0.z, rw0.w, h1, l1);
            *(uint2*)&dsm[WH + r0i + k2] = make_uint2(h0, h1);
            *(uint2*)&dsm[WL + r0i + k2] = make_uint2(l0, l1);
            k2 = c1k >> 1;
            bfsplit2(ra1.x, ra1.y, h0, l0); bfsplit2(ra1.z, ra1.w, h1, l1);
            *(uint2*)&dsm[AH + r1i + k2] = make_uint2(h0, h1);
            *(uint2*)&dsm[AL + r1i + k2] = make_uint2(l0, l1);
            bfsplit2(rw1.x, rw1.y, h0, l0); bfsplit2(rw1.z, rw1.w, h1, l1);
            *(uint2*)&dsm[WH + r1i + k2] = make_uint2(h0, h1);
            *(uint2*)&dsm[WL + r1i + k2] = make_uint2(l0, l1);
        }
        __syncthreads();

        if (kt + 1 < niter) {
            const int kg = (kt + 1) * 16;
            ra0 = ld_guard4(A + (size_t)rm0 * K + kg + c0k, kg + c0k, K);
            ra1 = ld_guard4(A + (size_t)rm1 * K + kg + c1k, kg + c1k, K);
            rw0 = ld_guard4(W + (size_t)(n0 + c0r) * K + kg + c0k, kg + c0k, K);
            rw1 = ld_guard4(W + (size_t)(n0 + c1r) * K + kg + c1k, kg + c1k, K);
        }

        uint32_t bh[4][2], bl[4][2];
#pragma unroll
        for (int jp = 0; jp < 2; jp++) {
            uint32_t r[4];
            uint32_t a = sbase + (WH + (bo + wn + jp * 16 + wrow) * 12 + wk2) * 4;
            ldsm_x4(r, a);
            bh[jp*2][0] = r[0]; bh[jp*2][1] = r[1];
            bh[jp*2+1][0] = r[2]; bh[jp*2+1][1] = r[3];
            ldsm_x4(r, a + (WL - WH) * 4);
            bl[jp*2][0] = r[0]; bl[jp*2][1] = r[1];
            bl[jp*2+1][0] = r[2]; bl[jp*2+1][1] = r[3];
        }
#pragma unroll
        for (int mi = 0; mi < 4; mi++) {
            uint32_t ah[4], al[4];
            uint32_t a = sbase + (AH + (bo + wm + mi * 16 + arow) * 12 + ak2) * 4;
            ldsm_x4(ah, a);
            ldsm_x4(al, a + (AL - AH) * 4);
#pragma unroll
            for (int j = 0; j < 4; j++) {
                mma_bf16(acc[mi][j], ah, bh[j]);
                mma_bf16(acc[mi][j], al, bh[j]);
                mma_bf16(acc[mi][j], ah, bl[j]);
            }
        }
    }

#pragma unroll
    for (int i = 0; i < 4; i++) {
        int lr0 = wm + i * 16 + gid;
        int g0 = sridx[lr0], g1 = sridx[lr0 + 8];
#pragma unroll
        for (int j = 0; j < 4; j++) {
            int col = n0 + wn + j * 8 + tig * 2;
            float b0 = bias[col], b1 = bias[col + 1];
            if (g0 >= 0)
                *(float2*)&C[(size_t)g0 * N + col] =
                    make_float2(acc[i][j][0] + b0, acc[i][j][1] + b1);
            if (g1 >= 0)
                *(float2*)&C[(size_t)g1 * N + col] =
                    make_float2(acc[i][j][2] + b0, acc[i][j][3] + b1);
        }
    }
}

// ---------------- software grid barrier ----------------
__device__ __forceinline__ void grid_sync(unsigned* bar, int ncta, unsigned* gen)
{
    __syncthreads();
    if (threadIdx.x == 0) {
        unsigned target = *gen + 1u;
        __threadfence();
        unsigned arr = atomicAdd(&bar[0], 1u);
        if (arr == (unsigned)(ncta - 1)) {
            atomicExch(&bar[0], 0u);
            __threadfence();
            atomicExch(&bar[1], target);
        } else {
            while (*(volatile unsigned*)&bar[1] < target) { }
        }
        __threadfence();
        *gen = target;
    }
    __syncthreads();
}

// ---------------- persistent GRU: bf16x3 LDSM phase1, packed-h staging ----
// Phase2 writes h as fp32 (exact hold) AND packed bf16 hi/lo; staging copies.
// smem u32 layout: WH[SLABS][96][12] | WL | HH[SLABS][128][12] | HL.
template<int H, int G3, int T, int NCT, int KS, int KC, int OCC>
__global__ __launch_bounds__(256, OCC) void gru_persistent(
    const float* __restrict__ xp, const float* __restrict__ w_hh,
    const float* __restrict__ b_hh, float* __restrict__ hbuf,
    uint32_t* __restrict__ hpk_hi, uint32_t* __restrict__ hpk_lo,
    float* __restrict__ part, float* __restrict__ out,
    const int* __restrict__ perm, const int* __restrict__ cnt,
    unsigned* __restrict__ bar)
{
    constexpr int NCTA  = 2 * NCT * KS;
    constexpr int H2    = H / 2;
    constexpr int SLABS = KC / 16;
    constexpr int WHo = 0;
    constexpr int WLo = SLABS * 96 * 12;
    constexpr int HHo = 2 * WLo;
    constexpr int HLo = HHo + SLABS * 128 * 12;
    extern __shared__ uint32_t sm[];

    const int cta = blockIdx.x;
    const int d   = cta / (NCT * KS);
    const int ct  = (cta % (NCT * KS)) / KS;
    const int ks  = cta % KS;
    const int c0  = ct * 96;
    const int k0  = ks * KC;
    const int tid = threadIdx.x;
    const int wid = tid / 32, lane = tid % 32;
    const int gid = lane >> 2, tig = lane & 3;
    const int wm  = (wid >> 1) * 32;
    const int wn  = (wid & 1) * 48;
    const int quad = lane >> 3, lrow = lane & 7;
    const int arow = ((quad & 1) << 3) + lrow;
    const int ak2  = (quad >> 1) * 4;
    const int wrow = ((quad >> 1) << 3) + lrow;
    const int wk2  = (quad & 1) * 4;
    const uint32_t sbase = (uint32_t)__cvta_generic_to_shared(sm);

    // W tile -> smem bf16 hi/lo (once)
    for (int e = tid; e < 96 * (KC / 2); e += 256) {
        int c = e / (KC / 2), k2 = e % (KC / 2);
        int slab = k2 >> 3, k2l = k2 & 7;
        const float* wp = w_hh + ((size_t)d * G3 + c0 + c) * H + k0 + 2 * k2;
        uint32_t h, l;
        bfsplit2(wp[0], wp[1], h, l);
        sm[WHo + slab * 1152 + c * 12 + k2l] = h;
        sm[WLo + slab * 1152 + c * 12 + k2l] = l;
    }
    __syncthreads();

    unsigned gen = 0;
    const int nth = NCTA * 256;
    const int kofs2 = k0 >> 1;

    for (int t = 0; t < T; t++) {
        const int cnt0 = cnt[t];
        const int cnt1 = cnt[T - 1 - t];
        const int cd   = (d == 0) ? cnt0 : cnt1;
        const int rc   = (cd + 31) & ~31;

        // stage h slice: pure copies from packed arrays
        for (int e = tid; e < rc * SLABS; e += 256) {
            int slab = e % SLABS, row = e / SLABS;
            size_t gbase = ((size_t)d * B + row) * H2 + kofs2 + slab * 8;
            int o = slab * 1536 + row * 12;
            uint4 a0 = *(const uint4*)&hpk_hi[gbase];
            uint4 a1 = *(const uint4*)&hpk_hi[gbase + 4];
            *(uint4*)&sm[HHo + o]     = a0;
            *(uint4*)&sm[HHo + o + 4] = a1;
            uint4 b0 = *(const uint4*)&hpk_lo[gbase];
            uint4 b1 = *(const uint4*)&hpk_lo[gbase + 4];
            *(uint4*)&sm[HLo + o]     = b0;
            *(uint4*)&sm[HLo + o + 4] = b1;
        }
        __syncthreads();

        if (wm < cd) {
            float acc[2][6][4];
#pragma unroll
            for (int i = 0; i < 2; i++)
#pragma unroll
                for (int j = 0; j < 6; j++)
#pragma unroll
                    for (int c = 0; c < 4; c++) acc[i][j][c] = 0.f;

#pragma unroll
            for (int s = 0; s < SLABS; s++) {
                uint32_t bh[6][2], bl[6][2];
#pragma unroll
                for (int jp = 0; jp < 3; jp++) {
                    uint32_t r[4];
                    uint32_t a = sbase + (WHo + s * 1152 + (wn + jp * 16 + wrow) * 12 + wk2) * 4;
                    ldsm_x4(r, a);
                    bh[jp*2][0] = r[0]; bh[jp*2][1] = r[1];
                    bh[jp*2+1][0] = r[2]; bh[jp*2+1][1] = r[3];
                    ldsm_x4(r, a + (WLo - WHo) * 4);
                    bl[jp*2][0] = r[0]; bl[jp*2][1] = r[1];
                    bl[jp*2+1][0] = r[2]; bl[jp*2+1][1] = r[3];
                }
#pragma unroll
                for (int mi = 0; mi < 2; mi++) {
                    uint32_t ah[4], al[4];
                    uint32_t a = sbase + (HHo + s * 1536 + (wm + mi * 16 + arow) * 12 + ak2) * 4;
                    ldsm_x4(ah, a);
                    ldsm_x4(al, a + (HLo - HHo) * 4);
#pragma unroll
                    for (int j = 0; j < 6; j++) {
                        mma_bf16(acc[mi][j], ah, bh[j]);
                        mma_bf16(acc[mi][j], al, bh[j]);
                        mma_bf16(acc[mi][j], ah, bl[j]);
                    }
                }
            }
#pragma unroll
            for (int mi = 0; mi < 2; mi++) {
                int r = wm + mi * 16 + gid;
#pragma unroll
                for (int j = 0; j < 6; j++) {
                    int col = c0 + wn + j * 8 + tig * 2;
                    float* p0 = part + (((size_t)ks * 2 + d) * B + r) * G3 + col;
                    float* p1 = part + (((size_t)ks * 2 + d) * B + r + 8) * G3 + col;
                    *(float2*)p0 = make_float2(acc[mi][j][0], acc[mi][j][1]);
                    *(float2*)p1 = make_float2(acc[mi][j][2], acc[mi][j][3]);
                }
            }
        }
        grid_sync(bar, NCTA, &gen);

        // phase2: valid elements only, 2 consecutive j per thread
        const int n0e = cnt0 * H2;
        const int total = n0e + cnt1 * H2;
        for (int it = cta * 256 + tid; it < total; it += nth) {
            int dd = (it >= n0e);
            int loc = dd ? (it - n0e) : it;
            int rr = loc / H2, j = (loc % H2) * 2;
            int te = dd ? (T - 1 - t) : t;
            int bo = perm[rr];
            float2 hold = *(const float2*)&hbuf[((size_t)dd * B + rr) * H + j];
            float2 hpr = make_float2(0.f, 0.f);
            float2 hpz = make_float2(0.f, 0.f);
            float2 hpn = make_float2(0.f, 0.f);
#pragma unroll
            for (int s = 0; s < KS; s++) {
                const float* pb = part + (((size_t)s * 2 + dd) * B + rr) * G3;
                float2 v;
                v = *(const float2*)(pb + j);         hpr.x += v.x; hpr.y += v.y;
                v = *(const float2*)(pb + H + j);     hpz.x += v.x; hpz.y += v.y;
                v = *(const float2*)(pb + 2 * H + j); hpn.x += v.x; hpn.y += v.y;
            }
            const float* bb = b_hh + (size_t)dd * G3;
            float2 br = *(const float2*)(bb + j);
            float2 bz = *(const float2*)(bb + H + j);
            float2 bn = *(const float2*)(bb + 2 * H + j);
            const float* xr = xp + ((size_t)bo * T + te) * (2 * G3) + (size_t)dd * G3;
            float2 xrv = *(const float2*)(xr + j);
            float2 xzv = *(const float2*)(xr + H + j);
            float2 xnv = *(const float2*)(xr + 2 * H + j);
            float rg0 = fast_sigmoid(xrv.x + hpr.x + br.x);
            float rg1 = fast_sigmoid(xrv.y + hpr.y + br.y);
            float zg0 = fast_sigmoid(xzv.x + hpz.x + bz.x);
            float zg1 = fast_sigmoid(xzv.y + hpz.y + bz.y);
            float ng0 = fast_tanh(xnv.x + rg0 * (hpn.x + bn.x));
            float ng1 = fast_tanh(xnv.y + rg1 * (hpn.y + bn.y));
            float2 hnew = make_float2((1.f - zg0) * ng0 + zg0 * hold.x,
                                      (1.f - zg1) * ng1 + zg1 * hold.y);
            *(float2*)&hbuf[((size_t)dd * B + rr) * H + j] = hnew;
            uint32_t ph, pl;
            bfsplit2(hnew.x, hnew.y, ph, pl);
            hpk_hi[((size_t)dd * B + rr) * H2 + (j >> 1)] = ph;
            hpk_lo[((size_t)dd * B + rr) * H2 + (j >> 1)] = pl;
            *(float2*)&out[((size_t)bo * T + te) * (2 * H) + dd * H + j] = hnew;
        }
        grid_sync(bar, NCTA, &gen);
    }
}

// ---------------- segment means ----------------
__global__ __launch_bounds__(256) void seg_mean_kernel(
    const float* __restrict__ vf, const float* __restrict__ loc,
    const int* __restrict__ v_len,
    float* __restrict__ lmean, float* __restrict__ rmean, float* __restrict__ cat)
{
    const int b = blockIdx.x;
    const int col = blockIdx.y * 256 + threadIdx.x;
    const int vl = v_len[b];
    const float scale = (float)(vl - 1);
    const float l0 = loc[b * 2], l1 = loc[b * 2 + 1];
    const int cond = (l0 <= l1);
    const float lhi = cond ? l0 : 0.f;
    const float rlo = cond ? l1 : 1.f;
    const int lend   = (int)floorf(lhi * scale);
    const int rstart = (int)floorf(rlo * scale);
    const int rend   = vl - 1;
    const int ok_l = (0 <= lend);
    const int ok_r = (rstart <= rend);

    float ls = 0.f, rs = 0.f, gs = 0.f;
    for (int t = 0; t < vl; t++) {
        float v = vf[((size_t)b * TV + t) * 1024 + col];
        gs += v;
        if (ok_l && t <= lend) ls += v;
        if (ok_r && t >= rstart) rs += v;
    }
    float lcnt = ok_l ? (float)(lend + 1) : 1.f;
    float rcnt = ok_r ? (float)(rend - rstart + 1) : 1.f;
    if (lcnt < 1.f) lcnt = 1.f;
    if (rcnt < 1.f) rcnt = 1.f;
    lmean[b * 1024 + col] = ls / lcnt;
    rmean[b * 1024 + col] = rs / rcnt;
    cat[(size_t)b * NCAT + 512 + col] = gs / (float)vl;
}

// ---------------- gather sen_fea ----------------
__global__ void gather_senfea(const float* __restrict__ words,
                              const int* __restrict__ lens,
                              float* __restrict__ out_sf, float* __restrict__ cat)
{
    const int b = blockIdx.x;
    const int t = lens[b] - 1;
    for (int c = threadIdx.x; c < 2 * SHID; c += blockDim.x) {
        float v = words[((size_t)b * TS + t) * (2 * SHID) + c];
        out_sf[(size_t)b * (2 * SHID) + c] = v;
        cat[(size_t)b * NCAT + c] = v;
    }
}

// ---------------- small GEMM with epilogue ----------------
__global__ __launch_bounds__(256) void gemm_small(
    const float* __restrict__ A, const float* __restrict__ W,
    const float* __restrict__ bias, const float* __restrict__ mul, int mulLd,
    float* __restrict__ C, int ldC, int M, int N, int K, int relu)
{
    const int n0 = blockIdx.x * 32, m0 = blockIdx.y * 32;
    __shared__ __align__(16) float As[32][34];
    __shared__ __align__(16) float Wsm[32][34];
    const int tid = threadIdx.x, ty = tid / 16, tx = tid % 16;
    float acc[2][2] = {{0.f, 0.f}, {0.f, 0.f}};

    for (int k0 = 0; k0 < K; k0 += 32) {
        for (int e = tid; e < 1024; e += 256) {
            int r = e / 32, k = e % 32;
            int kg = k0 + k;
            As[k][r]  = (kg < K) ? A[(size_t)(m0 + r) * K + kg] : 0.f;
            Wsm[k][r] = (kg < K) ? W[(size_t)(n0 + r) * K + kg] : 0.f;
        }
        __syncthreads();
#pragma unroll
        for (int k = 0; k < 32; k++) {
            float2 av = *(const float2*)&As[k][ty * 2];
            float2 wv = *(const float2*)&Wsm[k][tx * 2];
            acc[0][0] += av.x * wv.x;  acc[0][1] += av.x * wv.y;
            acc[1][0] += av.y * wv.x;  acc[1][1] += av.y * wv.y;
        }
        __syncthreads();
    }
#pragma unroll
    for (int i = 0; i < 2; i++) {
        int m = m0 + ty * 2 + i;
#pragma unroll
        for (int j = 0; j < 2; j++) {
            int n = n0 + tx * 2 + j;
            float v = acc[i][j] + bias[n];
            if (mul) v *= mul[(size_t)m * mulLd + n];
            if (relu) v = fmaxf(v, 0.f);
            C[(size_t)m * ldC + n] = v;
        }
    }
}

// ---------------- launch ----------------
extern "C" void kernel_launch(void* const* d_in, const int* in_sizes, int n_in,
                              void* d_out, int out_size)
{
    const float* gv     = (const float*)d_in[1];
    const float* sen    = (const float*)d_in[2];
    const float* loc    = (const float*)d_in[5];
    const int*   lens   = (const int*)  d_in[6];
    const int*   v_len  = (const int*)  d_in[7];
    const float* v_w_ih = (const float*)d_in[8];
    const float* v_w_hh = (const float*)d_in[9];
    const float* v_b_ih = (const float*)d_in[10];
    const float* v_b_hh = (const float*)d_in[11];
    const float* s_w_ih = (const float*)d_in[12];
    const float* s_w_hh = (const float*)d_in[13];
    const float* s_b_ih = (const float*)d_in[14];
    const float* s_b_hh = (const float*)d_in[15];
    const float* fc1_w  = (const float*)d_in[16];
    const float* fc1_b  = (const float*)d_in[17];
    const float* fc2_w  = (const float*)d_in[18];
    const float* fc2_b  = (const float*)d_in[19];
    const float* fc3_w  = (const float*)d_in[20];
    const float* fc3_b  = (const float*)d_in[21];
    const float* fc4_w  = (const float*)d_in[22];
    const float* fc4_b  = (const float*)d_in[23];

    float* out    = (float*)d_out;
    float* out_vf = out;
    float* out_sf = out + VF_ELEMS;
    float* out_ft = out + VF_ELEMS + SF_ELEMS;

    float *xp_v, *xp_s, *h_v, *h_s, *part_v, *part_s, *words;
    float *lmean, *rmean, *cat, *sproj;
    uint32_t *phv, *plv, *phs, *pls;
    int *perm_v, *lenp_v, *perm_s, *lenp_s, *cnt_v, *cnt_s;
    int *ridx_v, *ridx_s, *nv;
    unsigned* bar;
    cudaGetSymbolAddress((void**)&xp_v,   g_xp_v);
    cudaGetSymbolAddress((void**)&xp_s,   g_xp_s);
    cudaGetSymbolAddress((void**)&h_v,    g_h_v);
    cudaGetSymbolAddress((void**)&h_s,    g_h_s);
    cudaGetSymbolAddress((void**)&phv,    g_hpk_hi_v);
    cudaGetSymbolAddress((void**)&plv,    g_hpk_lo_v);
    cudaGetSymbolAddress((void**)&phs,    g_hpk_hi_s);
    cudaGetSymbolAddress((void**)&pls,    g_hpk_lo_s);
    cudaGetSymbolAddress((void**)&part_v, g_part_v);
    cudaGetSymbolAddress((void**)&part_s, g_part_s);
    cudaGetSymbolAddress((void**)&words,  g_words);
    cudaGetSymbolAddress((void**)&lmean,  g_lmean);
    cudaGetSymbolAddress((void**)&rmean,  g_rmean);
    cudaGetSymbolAddress((void**)&cat,    g_cat);
    cudaGetSymbolAddress((void**)&sproj,  g_sproj);
    cudaGetSymbolAddress((void**)&perm_v, g_perm_v);
    cudaGetSymbolAddress((void**)&lenp_v, g_lenp_v);
    cudaGetSymbolAddress((void**)&perm_s, g_perm_s);
    cudaGetSymbolAddress((void**)&lenp_s, g_lenp_s);
    cudaGetSymbolAddress((void**)&cnt_v,  g_cnt_v);
    cudaGetSymbolAddress((void**)&cnt_s,  g_cnt_s);
    cudaGetSymbolAddress((void**)&ridx_v, g_ridx_v);
    cudaGetSymbolAddress((void**)&ridx_s, g_ridx_s);
    cudaGetSymbolAddress((void**)&nv,     g_nv);
    cudaGetSymbolAddress((void**)&bar,    g_bar);

    // visual: SLABS=8 -> (2*9216 + 2*12288)*4 = 172032 B, 1 CTA/SM, 128 CTAs
    const int VGRU_SMEM = (2 * 8 * 96 * 12 + 2 * 8 * 128 * 12) * 4;
    // sentence: SLABS=4 -> 86016 B, 2 CTAs/SM, 64 CTAs
    const int SGRU_SMEM = (2 * 4 * 96 * 12 + 2 * 4 * 128 * 12) * 4;
    cudaFuncSetAttribute(gru_persistent<512, 1536, 256, 16, 4, 128, 1>,
                         cudaFuncAttributeMaxDynamicSharedMemorySize, VGRU_SMEM);
    cudaFuncSetAttribute(gru_persistent<256, 768, 40, 8, 4, 64, 2>,
                         cudaFuncAttributeMaxDynamicSharedMemorySize, SGRU_SMEM);
    cudaFuncSetAttribute(gemm_bf16x3,
                         cudaFuncAttributeMaxDynamicSharedMemorySize, GEMM_SMEM);

    // 1. init
    sort_init_kernel<<<1, 128>>>(v_len, lens, perm_v, lenp_v, perm_s, lenp_s,
                                 cnt_v, cnt_s, ridx_v, ridx_s, nv, bar);
    zero_h_kernel<<<(2*B*VHID + 255) / 256, 256>>>(h_v, h_s, phv, plv, phs, pls);
    zero_out_kernel<<<(int)(VF_ELEMS/4 + 255) / 256, 256>>>((float4*)out_vf,
                                                            (int)(VF_ELEMS/4));

    // 2. input projections (3xBF16, row-compacted)
    gemm_bf16x3<<<dim3(3072/128, (B*TV)/128), 256, GEMM_SMEM>>>(
        gv,  v_w_ih, v_b_ih, xp_v, ridx_v, nv,     3072, VIN);
    gemm_bf16x3<<<dim3(1536/128, (B*TS)/128), 256, GEMM_SMEM>>>(
        sen, s_w_ih, s_b_ih, xp_s, ridx_s, nv + 1, 1536, SIN);

    // 3. persistent visual GRU (128 CTAs, KC=128, KS=4)
    gru_persistent<512, 1536, 256, 16, 4, 128, 1><<<128, 256, VGRU_SMEM>>>(
        xp_v, v_w_hh, v_b_hh, h_v, phv, plv, part_v, out_vf, perm_v, cnt_v, bar);

    // 4. persistent sentence GRU (64 CTAs, KC=64, KS=4)
    gru_persistent<256, 768, 40, 8, 4, 64, 2><<<64, 256, SGRU_SMEM>>>(
        xp_s, s_w_hh, s_b_hh, h_s, phs, pls, part_s, words, perm_s, cnt_s, bar + 2);

    // 5. sen_fea gather
    gather_senfea<<<B, 256>>>(words, lens, out_sf, cat);

    // 6. segment means + global mean
    seg_mean_kernel<<<dim3(B, 4), 256>>>(out_vf, loc, v_len, lmean, rmean, cat);

    // 7. FC stack
    gemm_small<<<dim3(LCROSS/32, B/32), 256>>>(out_sf, fc2_w, fc2_b, nullptr, 0,
                                               sproj, LCROSS, B, LCROSS, 2*SHID, 0);
    gemm_small<<<dim3(LCROSS/32, B/32), 256>>>(lmean, fc1_w, fc1_b, sproj, LCROSS,
                                               cat + 1536, NCAT, B, LCROSS, 2*VHID, 1);
    gemm_small<<<dim3(LCROSS/32, B/32), 256>>>(rmean, fc1_w, fc1_b, sproj, LCROSS,
                                               cat + 2048, NCAT, B, LCROSS, 2*VHID, 1);
    gemm_small<<<dim3(NLOC/32, B/32), 256>>>(loc, fc3_w, fc3_b, nullptr, 0,
                                             cat + 2560, NCAT, B, NLOC, 2, 1);
    gemm_small<<<dim3(NFEAT/32, B/32), 256>>>(cat, fc4_w, fc4_b, nullptr, 0,
                                              out_ft, NFEAT, B, NFEAT, NCAT, 1);
}

// round 15
// speedup vs baseline: 1.0632x; 1.0632x over previous
#include <cuda_runtime.h>
#include <cuda_bf16.h>
#include <math.h>
#include <stdint.h>

// ---------------- problem constants ----------------
#define B        128
#define TV       256
#define TS       40
#define VIN      1024
#define VHID     512
#define SIN      300
#define SHID     256
#define NCAT     2624
#define NFEAT    1024
#define LCROSS   512
#define NLOC     64

#define VF_ELEMS   ((size_t)B*TV*2*VHID)
#define SF_ELEMS   ((size_t)B*2*SHID)

// ---------------- scratch (__device__ globals) ----------------
__device__ float g_xp_v[(size_t)B*TV*3072];
__device__ float g_xp_s[(size_t)B*TS*1536];
__device__ float g_h_v[2*B*VHID];
__device__ float g_h_s[2*B*SHID];
__device__ uint32_t g_hpk_hi_v[2*B*VHID/2], g_hpk_lo_v[2*B*VHID/2];
__device__ uint32_t g_hpk_hi_s[2*B*SHID/2], g_hpk_lo_s[2*B*SHID/2];
__device__ float g_part_v[8*2*B*1536];
__device__ float g_part_s[4*2*B*768];
__device__ float g_words[(size_t)B*TS*2*SHID];
__device__ float g_lmean[B*1024];
__device__ float g_rmean[B*1024];
__device__ float g_cat[B*NCAT];
__device__ float g_sproj[B*LCROSS];
__device__ int   g_perm_v[B], g_lenp_v[B];
__device__ int   g_perm_s[B], g_lenp_s[B];
__device__ int   g_cnt_v[TV], g_cnt_s[TS];
__device__ int   g_ridx_v[B*TV], g_ridx_s[B*TS];
__device__ int   g_nv[2];
__device__ unsigned g_bar[4];

// ---------------- init ----------------
__global__ void sort_init_kernel(const int* __restrict__ v_len,
                                 const int* __restrict__ lens,
                                 int* pv, int* lv, int* ps, int* ls,
                                 int* cv, int* cs,
                                 int* ridxv, int* ridxs, int* nv,
                                 unsigned* bar)
{
    int i = threadIdx.x;
    if (i < 4) bar[i] = 0u;

    for (int e = i; e < B*TV; e += 128) ridxv[e] = -1;
    for (int e = i; e < B*TS; e += 128) ridxs[e] = -1;
    __syncthreads();

    int a = v_len[i], rank = 0;
    for (int j = 0; j < B; j++) {
        int c = v_len[j];
        rank += (c > a) || (c == a && j < i);
    }
    pv[rank] = i; lv[rank] = a;
    a = lens[i]; rank = 0;
    for (int j = 0; j < B; j++) {
        int c = lens[j];
        rank += (c > a) || (c == a && j < i);
    }
    ps[rank] = i; ls[rank] = a;

    for (int t = i; t < TV; t += 128) {
        int c = 0;
        for (int j = 0; j < B; j++) c += (v_len[j] > t);
        cv[t] = c;
    }
    for (int t = i; t < TS; t += 128) {
        int c = 0;
        for (int j = 0; j < B; j++) c += (lens[j] > t);
        cs[t] = c;
    }

    int offv = 0, offs = 0;
    for (int j = 0; j < i; j++) { offv += v_len[j]; offs += lens[j]; }
    int lv_i = v_len[i], ls_i = lens[i];
    for (int t = 0; t < lv_i; t++) ridxv[offv + t] = i * TV + t;
    for (int t = 0; t < ls_i; t++) ridxs[offs + t] = i * TS + t;
    if (i == B - 1) {
        nv[0] = offv + lv_i;
        nv[1] = offs + ls_i;
    }
}

__global__ void zero_h_kernel(float* hv, float* hs,
                              uint32_t* phv, uint32_t* plv,
                              uint32_t* phs, uint32_t* pls) {
    int i = blockIdx.x * blockDim.x + threadIdx.x;
    if (i < 2*B*VHID) hv[i] = 0.f;
    if (i < 2*B*SHID) hs[i] = 0.f;
    if (i < 2*B*VHID/2) { phv[i] = 0u; plv[i] = 0u; }
    if (i < 2*B*SHID/2) { phs[i] = 0u; pls[i] = 0u; }
}

__global__ void zero_out_kernel(float4* p, int n4) {
    int i = blockIdx.x * blockDim.x + threadIdx.x;
    if (i < n4) p[i] = make_float4(0.f, 0.f, 0.f, 0.f);
}

// ---------------- numeric helpers ----------------
__device__ __forceinline__ void mma_bf16(float* d, const uint32_t* a, const uint32_t* b) {
    asm volatile(
        "mma.sync.aligned.m16n8k16.row.col.f32.bf16.bf16.f32 "
        "{%0,%1,%2,%3}, {%4,%5,%6,%7}, {%8,%9}, {%0,%1,%2,%3};"
        : "+f"(d[0]), "+f"(d[1]), "+f"(d[2]), "+f"(d[3])
        : "r"(a[0]), "r"(a[1]), "r"(a[2]), "r"(a[3]), "r"(b[0]), "r"(b[1]));
}
__device__ __forceinline__ void ldsm_x4(uint32_t* r, uint32_t saddr) {
    asm volatile("ldmatrix.sync.aligned.m8n8.x4.shared.b16 {%0,%1,%2,%3}, [%4];"
                 : "=r"(r[0]), "=r"(r[1]), "=r"(r[2]), "=r"(r[3]) : "r"(saddr));
}
__device__ __forceinline__ uint32_t bfpack(__nv_bfloat16 lo, __nv_bfloat16 hi) {
    uint32_t l = __bfloat16_as_ushort(lo);
    uint32_t h = __bfloat16_as_ushort(hi);
    return l | (h << 16);
}
__device__ __forceinline__ void bfsplit2(float x0, float x1,
                                         uint32_t& hi, uint32_t& lo) {
    __nv_bfloat16 h0 = __float2bfloat16_rn(x0);
    __nv_bfloat16 h1 = __float2bfloat16_rn(x1);
    hi = bfpack(h0, h1);
    __nv_bfloat16 l0 = __float2bfloat16_rn(x0 - __bfloat162float(h0));
    __nv_bfloat16 l1 = __float2bfloat16_rn(x1 - __bfloat162float(h1));
    lo = bfpack(l0, l1);
}
__device__ __forceinline__ float4 ld_guard4(const float* p, int kg, int K) {
    if (kg + 4 <= K) return *(const float4*)p;
    float4 v;
    v.x = (kg     < K) ? p[0] : 0.f;
    v.y = (kg + 1 < K) ? p[1] : 0.f;
    v.z = (kg + 2 < K) ? p[2] : 0.f;
    v.w = (kg + 3 < K) ? p[3] : 0.f;
    return v;
}
__device__ __forceinline__ float fast_sigmoid(float x) {
    return __fdividef(1.f, 1.f + __expf(-x));
}
__device__ __forceinline__ float fast_tanh(float x) {
    return __fdividef(2.f, 1.f + __expf(-2.f * x)) - 1.f;
}

// ---------------- 3xBF16 tensor-core GEMM, row-compacted ----------
#define GEMM_SMEM (4 * 2 * 128 * 12 * 4)     // 49152 B
__global__ __launch_bounds__(256, 2) void gemm_bf16x3(
    const float* __restrict__ A, const float* __restrict__ W,
    const float* __restrict__ bias, float* __restrict__ C,
    const int* __restrict__ ridx, const int* __restrict__ nvp,
    int N, int K)
{
    extern __shared__ uint32_t dsm[];
    const int AH = 0, AL = 2*128*12, WH = 2*AL, WL = 3*AL;
    __shared__ int sridx[128];

    const int n0 = blockIdx.x * 128;
    const int m0 = blockIdx.y * 128;
    const int tid = threadIdx.x;

    const int nv = *nvp;
    if (m0 >= nv) return;

    if (tid < 128) sridx[tid] = ridx[m0 + tid];
    __syncthreads();

    const int wid  = tid / 32, lane = tid % 32;
    const int wm   = (wid / 4) * 64;
    const int wn   = (wid % 4) * 32;
    const int gid  = lane >> 2, tig = lane & 3;
    const int quad = lane >> 3, lrow = lane & 7;
    const int arow = ((quad & 1) << 3) + lrow;
    const int ak2  = (quad >> 1) * 4;
    const int wrow = ((quad >> 1) << 3) + lrow;
    const int wk2  = (quad & 1) * 4;
    const uint32_t sbase = (uint32_t)__cvta_generic_to_shared(dsm);
    const int niter = (K + 15) >> 4;

    const int c0r = tid >> 2,          c0k = (tid & 3) * 4;
    const int c1r = (tid + 256) >> 2,  c1k = ((tid + 256) & 3) * 4;
    const int rm0 = sridx[c0r] < 0 ? 0 : sridx[c0r];
    const int rm1 = sridx[c1r] < 0 ? 0 : sridx[c1r];

    float acc[4][4][4];
#pragma unroll
    for (int i = 0; i < 4; i++)
#pragma unroll
        for (int j = 0; j < 4; j++)
#pragma unroll
            for (int c = 0; c < 4; c++) acc[i][j][c] = 0.f;

    float4 ra0, ra1, rw0, rw1;
    ra0 = ld_guard4(A + (size_t)rm0 * K + c0k, c0k, K);
    ra1 = ld_guard4(A + (size_t)rm1 * K + c1k, c1k, K);
    rw0 = ld_guard4(W + (size_t)(n0 + c0r) * K + c0k, c0k, K);
    rw1 = ld_guard4(W + (size_t)(n0 + c1r) * K + c1k, c1k, K);

    for (int kt = 0; kt < niter; kt++) {
        const int buf = kt & 1;
        const int bo = buf * 128;
        {
            uint32_t h0, l0, h1, l1;
            int k2 = c0k >> 1;
            int r0i = (bo + c0r) * 12, r1i = (bo + c1r) * 12;
            bfsplit2(ra0.x, ra0.y, h0, l0); bfsplit2(ra0.z, ra0.w, h1, l1);
            *(uint2*)&dsm[AH + r0i + k2] = make_uint2(h0, h1);
            *(uint2*)&dsm[AL + r0i + k2] = make_uint2(l0, l1);
            bfsplit2(rw0.x, rw0.y, h0, l0); bfsplit2(rw0.z, rw0.w, h1, l1);
            *(uint2*)&dsm[WH + r0i + k2] = make_uint2(h0, h1);
            *(uint2*)&dsm[WL + r0i + k2] = make_uint2(l0, l1);
            k2 = c1k >> 1;
            bfsplit2(ra1.x, ra1.y, h0, l0); bfsplit2(ra1.z, ra1.w, h1, l1);
            *(uint2*)&dsm[AH + r1i + k2] = make_uint2(h0, h1);
            *(uint2*)&dsm[AL + r1i + k2] = make_uint2(l0, l1);
            bfsplit2(rw1.x, rw1.y, h0, l0); bfsplit2(rw1.z, rw1.w, h1, l1);
            *(uint2*)&dsm[WH + r1i + k2] = make_uint2(h0, h1);
            *(uint2*)&dsm[WL + r1i + k2] = make_uint2(l0, l1);
        }
        __syncthreads();

        if (kt + 1 < niter) {
            const int kg = (kt + 1) * 16;
            ra0 = ld_guard4(A + (size_t)rm0 * K + kg + c0k, kg + c0k, K);
            ra1 = ld_guard4(A + (size_t)rm1 * K + kg + c1k, kg + c1k, K);
            rw0 = ld_guard4(W + (size_t)(n0 + c0r) * K + kg + c0k, kg + c0k, K);
            rw1 = ld_guard4(W + (size_t)(n0 + c1r) * K + kg + c1k, kg + c1k, K);
        }

        uint32_t bh[4][2], bl[4][2];
#pragma unroll
        for (int jp = 0; jp < 2; jp++) {
            uint32_t r[4];
            uint32_t a = sbase + (WH + (bo + wn + jp * 16 + wrow) * 12 + wk2) * 4;
            ldsm_x4(r, a);
            bh[jp*2][0] = r[0]; bh[jp*2][1] = r[1];
            bh[jp*2+1][0] = r[2]; bh[jp*2+1][1] = r[3];
            ldsm_x4(r, a + (WL - WH) * 4);
            bl[jp*2][0] = r[0]; bl[jp*2][1] = r[1];
            bl[jp*2+1][0] = r[2]; bl[jp*2+1][1] = r[3];
        }
#pragma unroll
        for (int mi = 0; mi < 4; mi++) {
            uint32_t ah[4], al[4];
            uint32_t a = sbase + (AH + (bo + wm + mi * 16 + arow) * 12 + ak2) * 4;
            ldsm_x4(ah, a);
            ldsm_x4(al, a + (AL - AH) * 4);
#pragma unroll
            for (int j = 0; j < 4; j++) {
                mma_bf16(acc[mi][j], ah, bh[j]);
                mma_bf16(acc[mi][j], al, bh[j]);
                mma_bf16(acc[mi][j], ah, bl[j]);
            }
        }
    }

#pragma unroll
    for (int i = 0; i < 4; i++) {
        int lr0 = wm + i * 16 + gid;
        int g0 = sridx[lr0], g1 = sridx[lr0 + 8];
#pragma unroll
        for (int j = 0; j < 4; j++) {
            int col = n0 + wn + j * 8 + tig * 2;
            float b0 = bias[col], b1 = bias[col + 1];
            if (g0 >= 0)
                *(float2*)&C[(size_t)g0 * N + col] =
                    make_float2(acc[i][j][0] + b0, acc[i][j][1] + b1);
            if (g1 >= 0)
                *(float2*)&C[(size_t)g1 * N + col] =
                    make_float2(acc[i][j][2] + b0, acc[i][j][3] + b1);
        }
    }
}

// ---------------- software grid barrier ----------------
__device__ __forceinline__ void grid_sync(unsigned* bar, int ncta, unsigned* gen)
{
    __syncthreads();
    if (threadIdx.x == 0) {
        unsigned target = *gen + 1u;
        __threadfence();
        unsigned arr = atomicAdd(&bar[0], 1u);
        if (arr == (unsigned)(ncta - 1)) {
            atomicExch(&bar[0], 0u);
            __threadfence();
            atomicExch(&bar[1], target);
        } else {
            while (*(volatile unsigned*)&bar[1] < target) { }
        }
        __threadfence();
        *gen = target;
    }
    __syncthreads();
}

// ---------------- persistent GRU: bf16x3 LDSM phase1, packed-h staging ----
// R13 geometry (KS=8/KC=64 visual, 2 CTAs/SM) + packed-h staging from R14.
// smem u32: WH[SLABS][96][12] | WL | HH[SLABS][128][12] | HL.
template<int H, int G3, int T, int NCT, int KS, int KC, int OCC>
__global__ __launch_bounds__(256, OCC) void gru_persistent(
    const float* __restrict__ xp, const float* __restrict__ w_hh,
    const float* __restrict__ b_hh, float* __restrict__ hbuf,
    uint32_t* __restrict__ hpk_hi, uint32_t* __restrict__ hpk_lo,
    float* __restrict__ part, float* __restrict__ out,
    const int* __restrict__ perm, const int* __restrict__ cnt,
    unsigned* __restrict__ bar)
{
    constexpr int NCTA  = 2 * NCT * KS;
    constexpr int H2    = H / 2;
    constexpr int SLABS = KC / 16;
    constexpr int WHo = 0;
    constexpr int WLo = SLABS * 96 * 12;
    constexpr int HHo = 2 * WLo;
    constexpr int HLo = HHo + SLABS * 128 * 12;
    extern __shared__ uint32_t sm[];

    const int cta = blockIdx.x;
    const int d   = cta / (NCT * KS);
    const int ct  = (cta % (NCT * KS)) / KS;
    const int ks  = cta % KS;
    const int c0  = ct * 96;
    const int k0  = ks * KC;
    const int tid = threadIdx.x;
    const int wid = tid / 32, lane = tid % 32;
    const int gid = lane >> 2, tig = lane & 3;
    const int wm  = (wid >> 1) * 32;
    const int wn  = (wid & 1) * 48;
    const int quad = lane >> 3, lrow = lane & 7;
    const int arow = ((quad & 1) << 3) + lrow;
    const int ak2  = (quad >> 1) * 4;
    const int wrow = ((quad >> 1) << 3) + lrow;
    const int wk2  = (quad & 1) * 4;
    const uint32_t sbase = (uint32_t)__cvta_generic_to_shared(sm);

    // W tile -> smem bf16 hi/lo (once)
    for (int e = tid; e < 96 * (KC / 2); e += 256) {
        int c = e / (KC / 2), k2 = e % (KC / 2);
        int slab = k2 >> 3, k2l = k2 & 7;
        const float* wp = w_hh + ((size_t)d * G3 + c0 + c) * H + k0 + 2 * k2;
        uint32_t h, l;
        bfsplit2(wp[0], wp[1], h, l);
        sm[WHo + slab * 1152 + c * 12 + k2l] = h;
        sm[WLo + slab * 1152 + c * 12 + k2l] = l;
    }
    __syncthreads();

    unsigned gen = 0;
    const int nth = NCTA * 256;
    const int kofs2 = k0 >> 1;

    for (int t = 0; t < T; t++) {
        const int cnt0 = cnt[t];
        const int cnt1 = cnt[T - 1 - t];
        const int cd   = (d == 0) ? cnt0 : cnt1;
        const int rc   = (cd + 31) & ~31;

        // stage h slice: pure uint4 copies from packed arrays (SLABS*8 u32/row)
        for (int e = tid; e < rc * SLABS; e += 256) {
            int slab = e % SLABS, row = e / SLABS;
            size_t gbase = ((size_t)d * B + row) * H2 + kofs2 + slab * 8;
            int o = slab * 1536 + row * 12;
            uint4 a0 = *(const uint4*)&hpk_hi[gbase];
            uint4 a1 = *(const uint4*)&hpk_hi[gbase + 4];
            *(uint4*)&sm[HHo + o]     = a0;
            *(uint4*)&sm[HHo + o + 4] = a1;
            uint4 b0 = *(const uint4*)&hpk_lo[gbase];
            uint4 b1 = *(const uint4*)&hpk_lo[gbase + 4];
            *(uint4*)&sm[HLo + o]     = b0;
            *(uint4*)&sm[HLo + o + 4] = b1;
        }
        __syncthreads();

        if (wm < cd) {
            float acc[2][6][4];
#pragma unroll
            for (int i = 0; i < 2; i++)
#pragma unroll
                for (int j = 0; j < 6; j++)
#pragma unroll
                    for (int c = 0; c < 4; c++) acc[i][j][c] = 0.f;

#pragma unroll
            for (int s = 0; s < SLABS; s++) {
                uint32_t bh[6][2], bl[6][2];
#pragma unroll
                for (int jp = 0; jp < 3; jp++) {
                    uint32_t r[4];
                    uint32_t a = sbase + (WHo + s * 1152 + (wn + jp * 16 + wrow) * 12 + wk2) * 4;
                    ldsm_x4(r, a);
                    bh[jp*2][0] = r[0]; bh[jp*2][1] = r[1];
                    bh[jp*2+1][0] = r[2]; bh[jp*2+1][1] = r[3];
                    ldsm_x4(r, a + (WLo - WHo) * 4);
                    bl[jp*2][0] = r[0]; bl[jp*2][1] = r[1];
                    bl[jp*2+1][0] = r[2]; bl[jp*2+1][1] = r[3];
                }
#pragma unroll
                for (int mi = 0; mi < 2; mi++) {
                    uint32_t ah[4], al[4];
                    uint32_t a = sbase + (HHo + s * 1536 + (wm + mi * 16 + arow) * 12 + ak2) * 4;
                    ldsm_x4(ah, a);
                    ldsm_x4(al, a + (HLo - HHo) * 4);
#pragma unroll
                    for (int j = 0; j < 6; j++) {
                        mma_bf16(acc[mi][j], ah, bh[j]);
                        mma_bf16(acc[mi][j], al, bh[j]);
                        mma_bf16(acc[mi][j], ah, bl[j]);
                    }
                }
            }
#pragma unroll
            for (int mi = 0; mi < 2; mi++) {
                int r = wm + mi * 16 + gid;
#pragma unroll
                for (int j = 0; j < 6; j++) {
                    int col = c0 + wn + j * 8 + tig * 2;
                    float* p0 = part + (((size_t)ks * 2 + d) * B + r) * G3 + col;
                    float* p1 = part + (((size_t)ks * 2 + d) * B + r + 8) * G3 + col;
                    *(float2*)p0 = make_float2(acc[mi][j][0], acc[mi][j][1]);
                    *(float2*)p1 = make_float2(acc[mi][j][2], acc[mi][j][3]);
                }
            }
        }
        grid_sync(bar, NCTA, &gen);

        // phase2: valid elements only, 2 consecutive j per thread
        const int n0e = cnt0 * H2;
        const int total = n0e + cnt1 * H2;
        for (int it = cta * 256 + tid; it < total; it += nth) {
            int dd = (it >= n0e);
            int loc = dd ? (it - n0e) : it;
            int rr = loc / H2, j = (loc % H2) * 2;
            int te = dd ? (T - 1 - t) : t;
            int bo = perm[rr];
            float2 hold = *(const float2*)&hbuf[((size_t)dd * B + rr) * H + j];
            float2 hpr = make_float2(0.f, 0.f);
            float2 hpz = make_float2(0.f, 0.f);
            float2 hpn = make_float2(0.f, 0.f);
#pragma unroll
            for (int s = 0; s < KS; s++) {
                const float* pb = part + (((size_t)s * 2 + dd) * B + rr) * G3;
                float2 v;
                v = *(const float2*)(pb + j);         hpr.x += v.x; hpr.y += v.y;
                v = *(const float2*)(pb + H + j);     hpz.x += v.x; hpz.y += v.y;
                v = *(const float2*)(pb + 2 * H + j); hpn.x += v.x; hpn.y += v.y;
            }
            const float* bb = b_hh + (size_t)dd * G3;
            float2 br = *(const float2*)(bb + j);
            float2 bz = *(const float2*)(bb + H + j);
            float2 bn = *(const float2*)(bb + 2 * H + j);
            const float* xr = xp + ((size_t)bo * T + te) * (2 * G3) + (size_t)dd * G3;
            float2 xrv = *(const float2*)(xr + j);
            float2 xzv = *(const float2*)(xr + H + j);
            float2 xnv = *(const float2*)(xr + 2 * H + j);
            float rg0 = fast_sigmoid(xrv.x + hpr.x + br.x);
            float rg1 = fast_sigmoid(xrv.y + hpr.y + br.y);
            float zg0 = fast_sigmoid(xzv.x + hpz.x + bz.x);
            float zg1 = fast_sigmoid(xzv.y + hpz.y + bz.y);
            float ng0 = fast_tanh(xnv.x + rg0 * (hpn.x + bn.x));
            float ng1 = fast_tanh(xnv.y + rg1 * (hpn.y + bn.y));
            float2 hnew = make_float2((1.f - zg0) * ng0 + zg0 * hold.x,
                                      (1.f - zg1) * ng1 + zg1 * hold.y);
            *(float2*)&hbuf[((size_t)dd * B + rr) * H + j] = hnew;
            uint32_t ph, pl;
            bfsplit2(hnew.x, hnew.y, ph, pl);
            hpk_hi[((size_t)dd * B + rr) * H2 + (j >> 1)] = ph;
            hpk_lo[((size_t)dd * B + rr) * H2 + (j >> 1)] = pl;
            *(float2*)&out[((size_t)bo * T + te) * (2 * H) + dd * H + j] = hnew;
        }
        grid_sync(bar, NCTA, &gen);
    }
}

// ---------------- segment means ----------------
__global__ __launch_bounds__(256) void seg_mean_kernel(
    const float* __restrict__ vf, const float* __restrict__ loc,
    const int* __restrict__ v_len,
    float* __restrict__ lmean, float* __restrict__ rmean, float* __restrict__ cat)
{
    const int b = blockIdx.x;
    const int col = blockIdx.y * 256 + threadIdx.x;
    const int vl = v_len[b];
    const float scale = (float)(vl - 1);
    const float l0 = loc[b * 2], l1 = loc[b * 2 + 1];
    const int cond = (l0 <= l1);
    const float lhi = cond ? l0 : 0.f;
    const float rlo = cond ? l1 : 1.f;
    const int lend   = (int)floorf(lhi * scale);
    const int rstart = (int)floorf(rlo * scale);
    const int rend   = vl - 1;
    const int ok_l = (0 <= lend);
    const int ok_r = (rstart <= rend);

    float ls = 0.f, rs = 0.f, gs = 0.f;
    for (int t = 0; t < vl; t++) {
        float v = vf[((size_t)b * TV + t) * 1024 + col];
        gs += v;
        if (ok_l && t <= lend) ls += v;
        if (ok_r && t >= rstart) rs += v;
    }
    float lcnt = ok_l ? (float)(lend + 1) : 1.f;
    float rcnt = ok_r ? (float)(rend - rstart + 1) : 1.f;
    if (lcnt < 1.f) lcnt = 1.f;
    if (rcnt < 1.f) rcnt = 1.f;
    lmean[b * 1024 + col] = ls / lcnt;
    rmean[b * 1024 + col] = rs / rcnt;
    cat[(size_t)b * NCAT + 512 + col] = gs / (float)vl;
}

// ---------------- gather sen_fea ----------------
__global__ void gather_senfea(const float* __restrict__ words,
                              const int* __restrict__ lens,
                              float* __restrict__ out_sf, float* __restrict__ cat)
{
    const int b = blockIdx.x;
    const int t = lens[b] - 1;
    for (int c = threadIdx.x; c < 2 * SHID; c += blockDim.x) {
        float v = words[((size_t)b * TS + t) * (2 * SHID) + c];
        out_sf[(size_t)b * (2 * SHID) + c] = v;
        cat[(size_t)b * NCAT + c] = v;
    }
}

// ---------------- small GEMM with epilogue ----------------
__global__ __launch_bounds__(256) void gemm_small(
    const float* __restrict__ A, const float* __restrict__ W,
    const float* __restrict__ bias, const float* __restrict__ mul, int mulLd,
    float* __restrict__ C, int ldC, int M, int N, int K, int relu)
{
    const int n0 = blockIdx.x * 32, m0 = blockIdx.y * 32;
    __shared__ __align__(16) float As[32][34];
    __shared__ __align__(16) float Wsm[32][34];
    const int tid = threadIdx.x, ty = tid / 16, tx = tid % 16;
    float acc[2][2] = {{0.f, 0.f}, {0.f, 0.f}};

    for (int k0 = 0; k0 < K; k0 += 32) {
        for (int e = tid; e < 1024; e += 256) {
            int r = e / 32, k = e % 32;
            int kg = k0 + k;
            As[k][r]  = (kg < K) ? A[(size_t)(m0 + r) * K + kg] : 0.f;
            Wsm[k][r] = (kg < K) ? W[(size_t)(n0 + r) * K + kg] : 0.f;
        }
        __syncthreads();
#pragma unroll
        for (int k = 0; k < 32; k++) {
            float2 av = *(const float2*)&As[k][ty * 2];
            float2 wv = *(const float2*)&Wsm[k][tx * 2];
            acc[0][0] += av.x * wv.x;  acc[0][1] += av.x * wv.y;
            acc[1][0] += av.y * wv.x;  acc[1][1] += av.y * wv.y;
        }
        __syncthreads();
    }
#pragma unroll
    for (int i = 0; i < 2; i++) {
        int m = m0 + ty * 2 + i;
#pragma unroll
        for (int j = 0; j < 2; j++) {
            int n = n0 + tx * 2 + j;
            float v = acc[i][j] + bias[n];
            if (mul) v *= mul[(size_t)m * mulLd + n];
            if (relu) v = fmaxf(v, 0.f);
            C[(size_t)m * ldC + n] = v;
        }
    }
}

// ---------------- launch ----------------
extern "C" void kernel_launch(void* const* d_in, const int* in_sizes, int n_in,
                              void* d_out, int out_size)
{
    const float* gv     = (const float*)d_in[1];
    const float* sen    = (const float*)d_in[2];
    const float* loc    = (const float*)d_in[5];
    const int*   lens   = (const int*)  d_in[6];
    const int*   v_len  = (const int*)  d_in[7];
    const float* v_w_ih = (const float*)d_in[8];
    const float* v_w_hh = (const float*)d_in[9];
    const float* v_b_ih = (const float*)d_in[10];
    const float* v_b_hh = (const float*)d_in[11];
    const float* s_w_ih = (const float*)d_in[12];
    const float* s_w_hh = (const float*)d_in[13];
    const float* s_b_ih = (const float*)d_in[14];
    const float* s_b_hh = (const float*)d_in[15];
    const float* fc1_w  = (const float*)d_in[16];
    const float* fc1_b  = (const float*)d_in[17];
    const float* fc2_w  = (const float*)d_in[18];
    const float* fc2_b  = (const float*)d_in[19];
    const float* fc3_w  = (const float*)d_in[20];
    const float* fc3_b  = (const float*)d_in[21];
    const float* fc4_w  = (const float*)d_in[22];
    const float* fc4_b  = (const float*)d_in[23];

    float* out    = (float*)d_out;
    float* out_vf = out;
    float* out_sf = out + VF_ELEMS;
    float* out_ft = out + VF_ELEMS + SF_ELEMS;

    float *xp_v, *xp_s, *h_v, *h_s, *part_v, *part_s, *words;
    float *lmean, *rmean, *cat, *sproj;
    uint32_t *phv, *plv, *phs, *pls;
    int *perm_v, *lenp_v, *perm_s, *lenp_s, *cnt_v, *cnt_s;
    int *ridx_v, *ridx_s, *nv;
    unsigned* bar;
    cudaGetSymbolAddress((void**)&xp_v,   g_xp_v);
    cudaGetSymbolAddress((void**)&xp_s,   g_xp_s);
    cudaGetSymbolAddress((void**)&h_v,    g_h_v);
    cudaGetSymbolAddress((void**)&h_s,    g_h_s);
    cudaGetSymbolAddress((void**)&phv,    g_hpk_hi_v);
    cudaGetSymbolAddress((void**)&plv,    g_hpk_lo_v);
    cudaGetSymbolAddress((void**)&phs,    g_hpk_hi_s);
    cudaGetSymbolAddress((void**)&pls,    g_hpk_lo_s);
    cudaGetSymbolAddress((void**)&part_v, g_part_v);
    cudaGetSymbolAddress((void**)&part_s, g_part_s);
    cudaGetSymbolAddress((void**)&words,  g_words);
    cudaGetSymbolAddress((void**)&lmean,  g_lmean);
    cudaGetSymbolAddress((void**)&rmean,  g_rmean);
    cudaGetSymbolAddress((void**)&cat,    g_cat);
    cudaGetSymbolAddress((void**)&sproj,  g_sproj);
    cudaGetSymbolAddress((void**)&perm_v, g_perm_v);
    cudaGetSymbolAddress((void**)&lenp_v, g_lenp_v);
    cudaGetSymbolAddress((void**)&perm_s, g_perm_s);
    cudaGetSymbolAddress((void**)&lenp_s, g_lenp_s);
    cudaGetSymbolAddress((void**)&cnt_v,  g_cnt_v);
    cudaGetSymbolAddress((void**)&cnt_s,  g_cnt_s);
    cudaGetSymbolAddress((void**)&ridx_v, g_ridx_v);
    cudaGetSymbolAddress((void**)&ridx_s, g_ridx_s);
    cudaGetSymbolAddress((void**)&nv,     g_nv);
    cudaGetSymbolAddress((void**)&bar,    g_bar);

    // both GRUs: SLABS=4 -> (2*4608 + 2*6144)*4 = 86016 B, 2 CTAs/SM
    const int GRU_SMEM = (2 * 4 * 96 * 12 + 2 * 4 * 128 * 12) * 4;
    cudaFuncSetAttribute(gru_persistent<512, 1536, 256, 16, 8, 64, 2>,
                         cudaFuncAttributeMaxDynamicSharedMemorySize, GRU_SMEM);
    cudaFuncSetAttribute(gru_persistent<256, 768, 40, 8, 4, 64, 2>,
                         cudaFuncAttributeMaxDynamicSharedMemorySize, GRU_SMEM);
    cudaFuncSetAttribute(gemm_bf16x3,
                         cudaFuncAttributeMaxDynamicSharedMemorySize, GEMM_SMEM);

    // 1. init
    sort_init_kernel<<<1, 128>>>(v_len, lens, perm_v, lenp_v, perm_s, lenp_s,
                                 cnt_v, cnt_s, ridx_v, ridx_s, nv, bar);
    zero_h_kernel<<<(2*B*VHID + 255) / 256, 256>>>(h_v, h_s, phv, plv, phs, pls);
    zero_out_kernel<<<(int)(VF_ELEMS/4 + 255) / 256, 256>>>((float4*)out_vf,
                                                            (int)(VF_ELEMS/4));

    // 2. input projections (3xBF16, row-compacted)
    gemm_bf16x3<<<dim3(3072/128, (B*TV)/128), 256, GEMM_SMEM>>>(
        gv,  v_w_ih, v_b_ih, xp_v, ridx_v, nv,     3072, VIN);
    gemm_bf16x3<<<dim3(1536/128, (B*TS)/128), 256, GEMM_SMEM>>>(
        sen, s_w_ih, s_b_ih, xp_s, ridx_s, nv + 1, 1536, SIN);

    // 3. persistent visual GRU (256 CTAs, KS=8, KC=64, packed-h staging)
    gru_persistent<512, 1536, 256, 16, 8, 64, 2><<<256, 256, GRU_SMEM>>>(
        xp_v, v_w_hh, v_b_hh, h_v, phv, plv, part_v, out_vf, perm_v, cnt_v, bar);

    // 4. persistent sentence GRU (64 CTAs)
    gru_persistent<256, 768, 40, 8, 4, 64, 2><<<64, 256, GRU_SMEM>>>(
        xp_s, s_w_hh, s_b_hh, h_s, phs, pls, part_s, words, perm_s, cnt_s, bar + 2);

    // 5. sen_fea gather
    gather_senfea<<<B, 256>>>(words, lens, out_sf, cat);

    // 6. segment means + global mean
    seg_mean_kernel<<<dim3(B, 4), 256>>>(out_vf, loc, v_len, lmean, rmean, cat);

    // 7. FC stack
    gemm_small<<<dim3(LCROSS/32, B/32), 256>>>(out_sf, fc2_w, fc2_b, nullptr, 0,
                                               sproj, LCROSS, B, LCROSS, 2*SHID, 0);
    gemm_small<<<dim3(LCROSS/32, B/32), 256>>>(lmean, fc1_w, fc1_b, sproj, LCROSS,
                                               cat + 1536, NCAT, B, LCROSS, 2*VHID, 1);
    gemm_small<<<dim3(LCROSS/32, B/32), 256>>>(rmean, fc1_w, fc1_b, sproj, LCROSS,
                                               cat + 2048, NCAT, B, LCROSS, 2*VHID, 1);
    gemm_small<<<dim3(NLOC/32, B/32), 256>>>(loc, fc3_w, fc3_b, nullptr, 0,
                                             cat + 2560, NCAT, B, NLOC, 2, 1);
    gemm_small<<<dim3(NFEAT/32, B/32), 256>>>(cat, fc4_w, fc4_b, nullptr, 0,
                                              out_ft, NFEAT, B, NFEAT, NCAT, 1);
}

// round 16
// speedup vs baseline: 1.1099x; 1.0439x over previous
#include <cuda_runtime.h>
#include <cuda_bf16.h>
#include <math.h>
#include <stdint.h>

// ---------------- problem constants ----------------
#define B        128
#define TV       256
#define TS       40
#define VIN      1024
#define VHID     512
#define SIN      300
#define SHID     256
#define NCAT     2624
#define NFEAT    1024
#define LCROSS   512
#define NLOC     64

#define VF_ELEMS   ((size_t)B*TV*2*VHID)
#define SF_ELEMS   ((size_t)B*2*SHID)

// ---------------- scratch (__device__ globals) ----------------
__device__ float g_xp_v[(size_t)B*TV*3072];
__device__ float g_xp_s[(size_t)B*TS*1536];
__device__ float g_h_v[2*B*VHID];
__device__ float g_h_s[2*B*SHID];
__device__ uint32_t g_hpk_hi_v[2*B*VHID/2], g_hpk_lo_v[2*B*VHID/2];
__device__ uint32_t g_hpk_hi_s[2*B*SHID/2], g_hpk_lo_s[2*B*SHID/2];
__device__ float g_part_v[8*2*B*1536];
__device__ float g_part_s[4*2*B*768];
__device__ float g_words[(size_t)B*TS*2*SHID];
__device__ float g_lmean[B*1024];
__device__ float g_rmean[B*1024];
__device__ float g_cat[B*NCAT];
__device__ float g_sproj[B*LCROSS];
__device__ int   g_perm_v[B], g_lenp_v[B];
__device__ int   g_perm_s[B], g_lenp_s[B];
__device__ int   g_cnt_v[TV], g_cnt_s[TS];
__device__ int   g_ridx_v[B*TV], g_ridx_s[B*TS];
__device__ int   g_nv[2];
__device__ unsigned g_bar[8];                // 4 (cnt,gen) pairs: v_d0,v_d1,s_d0,s_d1

// ---------------- init ----------------
__global__ void sort_init_kernel(const int* __restrict__ v_len,
                                 const int* __restrict__ lens,
                                 int* pv, int* lv, int* ps, int* ls,
                                 int* cv, int* cs,
                                 int* ridxv, int* ridxs, int* nv,
                                 unsigned* bar)
{
    int i = threadIdx.x;
    if (i < 8) bar[i] = 0u;

    for (int e = i; e < B*TV; e += 128) ridxv[e] = -1;
    for (int e = i; e < B*TS; e += 128) ridxs[e] = -1;
    __syncthreads();

    int a = v_len[i], rank = 0;
    for (int j = 0; j < B; j++) {
        int c = v_len[j];
        rank += (c > a) || (c == a && j < i);
    }
    pv[rank] = i; lv[rank] = a;
    a = lens[i]; rank = 0;
    for (int j = 0; j < B; j++) {
        int c = lens[j];
        rank += (c > a) || (c == a && j < i);
    }
    ps[rank] = i; ls[rank] = a;

    for (int t = i; t < TV; t += 128) {
        int c = 0;
        for (int j = 0; j < B; j++) c += (v_len[j] > t);
        cv[t] = c;
    }
    for (int t = i; t < TS; t += 128) {
        int c = 0;
        for (int j = 0; j < B; j++) c += (lens[j] > t);
        cs[t] = c;
    }

    int offv = 0, offs = 0;
    for (int j = 0; j < i; j++) { offv += v_len[j]; offs += lens[j]; }
    int lv_i = v_len[i], ls_i = lens[i];
    for (int t = 0; t < lv_i; t++) ridxv[offv + t] = i * TV + t;
    for (int t = 0; t < ls_i; t++) ridxs[offs + t] = i * TS + t;
    if (i == B - 1) {
        nv[0] = offv + lv_i;
        nv[1] = offs + ls_i;
    }
}

__global__ void zero_h_kernel(float* hv, float* hs,
                              uint32_t* phv, uint32_t* plv,
                              uint32_t* phs, uint32_t* pls) {
    int i = blockIdx.x * blockDim.x + threadIdx.x;
    if (i < 2*B*VHID) hv[i] = 0.f;
    if (i < 2*B*SHID) hs[i] = 0.f;
    if (i < 2*B*VHID/2) { phv[i] = 0u; plv[i] = 0u; }
    if (i < 2*B*SHID/2) { phs[i] = 0u; pls[i] = 0u; }
}

__global__ void zero_out_kernel(float4* p, int n4) {
    int i = blockIdx.x * blockDim.x + threadIdx.x;
    if (i < n4) p[i] = make_float4(0.f, 0.f, 0.f, 0.f);
}

// ---------------- numeric helpers ----------------
__device__ __forceinline__ void mma_bf16(float* d, const uint32_t* a, const uint32_t* b) {
    asm volatile(
        "mma.sync.aligned.m16n8k16.row.col.f32.bf16.bf16.f32 "
        "{%0,%1,%2,%3}, {%4,%5,%6,%7}, {%8,%9}, {%0,%1,%2,%3};"
        : "+f"(d[0]), "+f"(d[1]), "+f"(d[2]), "+f"(d[3])
        : "r"(a[0]), "r"(a[1]), "r"(a[2]), "r"(a[3]), "r"(b[0]), "r"(b[1]));
}
__device__ __forceinline__ void ldsm_x4(uint32_t* r, uint32_t saddr) {
    asm volatile("ldmatrix.sync.aligned.m8n8.x4.shared.b16 {%0,%1,%2,%3}, [%4];"
                 : "=r"(r[0]), "=r"(r[1]), "=r"(r[2]), "=r"(r[3]) : "r"(saddr));
}
__device__ __forceinline__ uint32_t bfpack(__nv_bfloat16 lo, __nv_bfloat16 hi) {
    uint32_t l = __bfloat16_as_ushort(lo);
    uint32_t h = __bfloat16_as_ushort(hi);
    return l | (h << 16);
}
__device__ __forceinline__ void bfsplit2(float x0, float x1,
                                         uint32_t& hi, uint32_t& lo) {
    __nv_bfloat16 h0 = __float2bfloat16_rn(x0);
    __nv_bfloat16 h1 = __float2bfloat16_rn(x1);
    hi = bfpack(h0, h1);
    __nv_bfloat16 l0 = __float2bfloat16_rn(x0 - __bfloat162float(h0));
    __nv_bfloat16 l1 = __float2bfloat16_rn(x1 - __bfloat162float(h1));
    lo = bfpack(l0, l1);
}
__device__ __forceinline__ float4 ld_guard4(const float* p, int kg, int K) {
    if (kg + 4 <= K) return *(const float4*)p;
    float4 v;
    v.x = (kg     < K) ? p[0] : 0.f;
    v.y = (kg + 1 < K) ? p[1] : 0.f;
    v.z = (kg + 2 < K) ? p[2] : 0.f;
    v.w = (kg + 3 < K) ? p[3] : 0.f;
    return v;
}
__device__ __forceinline__ float fast_sigmoid(float x) {
    return __fdividef(1.f, 1.f + __expf(-x));
}
__device__ __forceinline__ float fast_tanh(float x) {
    return __fdividef(2.f, 1.f + __expf(-2.f * x)) - 1.f;
}

// ---------------- 3xBF16 tensor-core GEMM, row-compacted ----------
#define GEMM_SMEM (4 * 2 * 128 * 12 * 4)     // 49152 B
__global__ __launch_bounds__(256, 2) void gemm_bf16x3(
    const float* __restrict__ A, const float* __restrict__ W,
    const float* __restrict__ bias, float* __restrict__ C,
    const int* __restrict__ ridx, const int* __restrict__ nvp,
    int N, int K)
{
    extern __shared__ uint32_t dsm[];
    const int AH = 0, AL = 2*128*12, WH = 2*AL, WL = 3*AL;
    __shared__ int sridx[128];

    const int n0 = blockIdx.x * 128;
    const int m0 = blockIdx.y * 128;
    const int tid = threadIdx.x;

    const int nv = *nvp;
    if (m0 >= nv) return;

    if (tid < 128) sridx[tid] = ridx[m0 + tid];
    __syncthreads();

    const int wid  = tid / 32, lane = tid % 32;
    const int wm   = (wid / 4) * 64;
    const int wn   = (wid % 4) * 32;
    const int gid  = lane >> 2, tig = lane & 3;
    const int quad = lane >> 3, lrow = lane & 7;
    const int arow = ((quad & 1) << 3) + lrow;
    const int ak2  = (quad >> 1) * 4;
    const int wrow = ((quad >> 1) << 3) + lrow;
    const int wk2  = (quad & 1) * 4;
    const uint32_t sbase = (uint32_t)__cvta_generic_to_shared(dsm);
    const int niter = (K + 15) >> 4;

    const int c0r = tid >> 2,          c0k = (tid & 3) * 4;
    const int c1r = (tid + 256) >> 2,  c1k = ((tid + 256) & 3) * 4;
    const int rm0 = sridx[c0r] < 0 ? 0 : sridx[c0r];
    const int rm1 = sridx[c1r] < 0 ? 0 : sridx[c1r];

    float acc[4][4][4];
#pragma unroll
    for (int i = 0; i < 4; i++)
#pragma unroll
        for (int j = 0; j < 4; j++)
#pragma unroll
            for (int c = 0; c < 4; c++) acc[i][j][c] = 0.f;

    float4 ra0, ra1, rw0, rw1;
    ra0 = ld_guard4(A + (size_t)rm0 * K + c0k, c0k, K);
    ra1 = ld_guard4(A + (size_t)rm1 * K + c1k, c1k, K);
    rw0 = ld_guard4(W + (size_t)(n0 + c0r) * K + c0k, c0k, K);
    rw1 = ld_guard4(W + (size_t)(n0 + c1r) * K + c1k, c1k, K);

    for (int kt = 0; kt < niter; kt++) {
        const int buf = kt & 1;
        const int bo = buf * 128;
        {
            uint32_t h0, l0, h1, l1;
            int k2 = c0k >> 1;
            int r0i = (bo + c0r) * 12, r1i = (bo + c1r) * 12;
            bfsplit2(ra0.x, ra0.y, h0, l0); bfsplit2(ra0.z, ra0.w, h1, l1);
            *(uint2*)&dsm[AH + r0i + k2] = make_uint2(h0, h1);
            *(uint2*)&dsm[AL + r0i + k2] = make_uint2(l0, l1);
            bfsplit2(rw0.x, rw0.y, h0, l0); bfsplit2(rw0.z, rw0.w, h1, l1);
            *(uint2*)&dsm[WH + r0i + k2] = make_uint2(h0, h1);
            *(uint2*)&dsm[WL + r0i + k2] = make_uint2(l0, l1);
            k2 = c1k >> 1;
            bfsplit2(ra1.x, ra1.y, h0, l0); bfsplit2(ra1.z, ra1.w, h1, l1);
            *(uint2*)&dsm[AH + r1i + k2] = make_uint2(h0, h1);
            *(uint2*)&dsm[AL + r1i + k2] = make_uint2(l0, l1);
            bfsplit2(rw1.x, rw1.y, h0, l0); bfsplit2(rw1.z, rw1.w, h1, l1);
            *(uint2*)&dsm[WH + r1i + k2] = make_uint2(h0, h1);
            *(uint2*)&dsm[WL + r1i + k2] = make_uint2(l0, l1);
        }
        __syncthreads();

        if (kt + 1 < niter) {
            const int kg = (kt + 1) * 16;
            ra0 = ld_guard4(A + (size_t)rm0 * K + kg + c0k, kg + c0k, K);
            ra1 = ld_guard4(A + (size_t)rm1 * K + kg + c1k, kg + c1k, K);
            rw0 = ld_guard4(W + (size_t)(n0 + c0r) * K + kg + c0k, kg + c0k, K);
            rw1 = ld_guard4(W + (size_t)(n0 + c1r) * K + kg + c1k, kg + c1k, K);
        }

        uint32_t bh[4][2], bl[4][2];
#pragma unroll
        for (int jp = 0; jp < 2; jp++) {
            uint32_t r[4];
            uint32_t a = sbase + (WH + (bo + wn + jp * 16 + wrow) * 12 + wk2) * 4;
            ldsm_x4(r, a);
            bh[jp*2][0] = r[0]; bh[jp*2][1] = r[1];
            bh[jp*2+1][0] = r[2]; bh[jp*2+1][1] = r[3];
            ldsm_x4(r, a + (WL - WH) * 4);
            bl[jp*2][0] = r[0]; bl[jp*2][1] = r[1];
            bl[jp*2+1][0] = r[2]; bl[jp*2+1][1] = r[3];
        }
#pragma unroll
        for (int mi = 0; mi < 4; mi++) {
            uint32_t ah[4], al[4];
            uint32_t a = sbase + (AH + (bo + wm + mi * 16 + arow) * 12 + ak2) * 4;
            ldsm_x4(ah, a);
            ldsm_x4(al, a + (AL - AH) * 4);
#pragma unroll
            for (int j = 0; j < 4; j++) {
                mma_bf16(acc[mi][j], ah, bh[j]);
                mma_bf16(acc[mi][j], al, bh[j]);
                mma_bf16(acc[mi][j], ah, bl[j]);
            }
        }
    }

#pragma unroll
    for (int i = 0; i < 4; i++) {
        int lr0 = wm + i * 16 + gid;
        int g0 = sridx[lr0], g1 = sridx[lr0 + 8];
#pragma unroll
        for (int j = 0; j < 4; j++) {
            int col = n0 + wn + j * 8 + tig * 2;
            float b0 = bias[col], b1 = bias[col + 1];
            if (g0 >= 0)
                *(float2*)&C[(size_t)g0 * N + col] =
                    make_float2(acc[i][j][0] + b0, acc[i][j][1] + b1);
            if (g1 >= 0)
                *(float2*)&C[(size_t)g1 * N + col] =
                    make_float2(acc[i][j][2] + b0, acc[i][j][3] + b1);
        }
    }
}

// ---------------- software grid barrier ----------------
__device__ __forceinline__ void grid_sync(unsigned* bar, int ncta, unsigned* gen)
{
    __syncthreads();
    if (threadIdx.x == 0) {
        unsigned target = *gen + 1u;
        __threadfence();
        unsigned arr = atomicAdd(&bar[0], 1u);
        if (arr == (unsigned)(ncta - 1)) {
            atomicExch(&bar[0], 0u);
            __threadfence();
            atomicExch(&bar[1], target);
        } else {
            while (*(volatile unsigned*)&bar[1] < target) { }
        }
        __threadfence();
        *gen = target;
    }
    __syncthreads();
}

// ---------------- persistent GRU: per-direction barriers + local phase2 ----
// Direction d's CTAs sync only among themselves; phase2 of direction d runs
// on direction-d CTAs; each direction iterates only te in [0, maxlen).
template<int H, int G3, int T, int NCT, int KS, int KC, int OCC>
__global__ __launch_bounds__(256, OCC) void gru_persistent(
    const float* __restrict__ xp, const float* __restrict__ w_hh,
    const float* __restrict__ b_hh, float* __restrict__ hbuf,
    uint32_t* __restrict__ hpk_hi, uint32_t* __restrict__ hpk_lo,
    float* __restrict__ part, float* __restrict__ out,
    const int* __restrict__ perm, const int* __restrict__ lenp,
    const int* __restrict__ cnt, unsigned* __restrict__ bar)
{
    constexpr int NCTAD = NCT * KS;          // CTAs per direction
    constexpr int H2    = H / 2;
    constexpr int SLABS = KC / 16;
    constexpr int WHo = 0;
    constexpr int WLo = SLABS * 96 * 12;
    constexpr int HHo = 2 * WLo;
    constexpr int HLo = HHo + SLABS * 128 * 12;
    extern __shared__ uint32_t sm[];

    const int cta  = blockIdx.x;
    const int d    = cta / NCTAD;
    const int ctad = cta % NCTAD;
    const int ct   = ctad / KS;
    const int ks   = ctad % KS;
    const int c0   = ct * 96;
    const int k0   = ks * KC;
    const int tid  = threadIdx.x;
    const int wid  = tid / 32, lane = tid % 32;
    const int gid  = lane >> 2, tig = lane & 3;
    const int wm   = (wid >> 1) * 32;
    const int wn   = (wid & 1) * 48;
    const int quad = lane >> 3, lrow = lane & 7;
    const int arow = ((quad & 1) << 3) + lrow;
    const int ak2  = (quad >> 1) * 4;
    const int wrow = ((quad >> 1) << 3) + lrow;
    const int wk2  = (quad & 1) * 4;
    const uint32_t sbase = (uint32_t)__cvta_generic_to_shared(sm);
    unsigned* mybar = bar + 2 * d;

    // W tile -> smem bf16 hi/lo (once)
    for (int e = tid; e < 96 * (KC / 2); e += 256) {
        int c = e / (KC / 2), k2 = e % (KC / 2);
        int slab = k2 >> 3, k2l = k2 & 7;
        const float* wp = w_hh + ((size_t)d * G3 + c0 + c) * H + k0 + 2 * k2;
        uint32_t h, l;
        bfsplit2(wp[0], wp[1], h, l);
        sm[WHo + slab * 1152 + c * 12 + k2l] = h;
        sm[WLo + slab * 1152 + c * 12 + k2l] = l;
    }
    __syncthreads();

    unsigned gen = 0;
    const int nthd  = NCTAD * 256;
    const int kofs2 = k0 >> 1;
    const int maxlen = lenp[0];

    for (int step = 0; step < maxlen; step++) {
        const int te = (d == 0) ? step : (maxlen - 1 - step);
        const int cd = cnt[te];
        const int rc = (cd + 31) & ~31;

        // stage h slice (packed, direction-private)
        for (int e = tid; e < rc * SLABS; e += 256) {
            int slab = e % SLABS, row = e / SLABS;
            size_t gbase = ((size_t)d * B + row) * H2 + kofs2 + slab * 8;
            int o = slab * 1536 + row * 12;
            uint4 a0 = *(const uint4*)&hpk_hi[gbase];
            uint4 a1 = *(const uint4*)&hpk_hi[gbase + 4];
            *(uint4*)&sm[HHo + o]     = a0;
            *(uint4*)&sm[HHo + o + 4] = a1;
            uint4 b0 = *(const uint4*)&hpk_lo[gbase];
            uint4 b1 = *(const uint4*)&hpk_lo[gbase + 4];
            *(uint4*)&sm[HLo + o]     = b0;
            *(uint4*)&sm[HLo + o + 4] = b1;
        }
        __syncthreads();

        if (wm < cd) {
            float acc[2][6][4];
#pragma unroll
            for (int i = 0; i < 2; i++)
#pragma unroll
                for (int j = 0; j < 6; j++)
#pragma unroll
                    for (int c = 0; c < 4; c++) acc[i][j][c] = 0.f;

#pragma unroll
            for (int s = 0; s < SLABS; s++) {
                uint32_t bh[6][2], bl[6][2];
#pragma unroll
                for (int jp = 0; jp < 3; jp++) {
                    uint32_t r[4];
                    uint32_t a = sbase + (WHo + s * 1152 + (wn + jp * 16 + wrow) * 12 + wk2) * 4;
                    ldsm_x4(r, a);
                    bh[jp*2][0] = r[0]; bh[jp*2][1] = r[1];
                    bh[jp*2+1][0] = r[2]; bh[jp*2+1][1] = r[3];
                    ldsm_x4(r, a + (WLo - WHo) * 4);
                    bl[jp*2][0] = r[0]; bl[jp*2][1] = r[1];
                    bl[jp*2+1][0] = r[2]; bl[jp*2+1][1] = r[3];
                }
#pragma unroll
                for (int mi = 0; mi < 2; mi++) {
                    uint32_t ah[4], al[4];
                    uint32_t a = sbase + (HHo + s * 1536 + (wm + mi * 16 + arow) * 12 + ak2) * 4;
                    ldsm_x4(ah, a);
                    ldsm_x4(al, a + (HLo - HHo) * 4);
#pragma unroll
                    for (int j = 0; j < 6; j++) {
                        mma_bf16(acc[mi][j], ah, bh[j]);
                        mma_bf16(acc[mi][j], al, bh[j]);
                        mma_bf16(acc[mi][j], ah, bl[j]);
                    }
                }
            }
#pragma unroll
            for (int mi = 0; mi < 2; mi++) {
                int r = wm + mi * 16 + gid;
#pragma unroll
                for (int j = 0; j < 6; j++) {
                    int col = c0 + wn + j * 8 + tig * 2;
                    float* p0 = part + (((size_t)ks * 2 + d) * B + r) * G3 + col;
                    float* p1 = part + (((size_t)ks * 2 + d) * B + r + 8) * G3 + col;
                    *(float2*)p0 = make_float2(acc[mi][j][0], acc[mi][j][1]);
                    *(float2*)p1 = make_float2(acc[mi][j][2], acc[mi][j][3]);
                }
            }
        }
        grid_sync(mybar, NCTAD, &gen);

        // phase2: own direction only, 2 consecutive j per thread
        const int total = cd * H2;
        for (int it = ctad * 256 + tid; it < total; it += nthd) {
            int rr = it / H2, j = (it % H2) * 2;
            int bo = perm[rr];
            float2 hold = *(const float2*)&hbuf[((size_t)d * B + rr) * H + j];
            float2 hpr = make_float2(0.f, 0.f);
            float2 hpz = make_float2(0.f, 0.f);
            float2 hpn = make_float2(0.f, 0.f);
#pragma unroll
            for (int s = 0; s < KS; s++) {
                const float* pb = part + (((size_t)s * 2 + d) * B + rr) * G3;
                float2 v;
                v = *(const float2*)(pb + j);         hpr.x += v.x; hpr.y += v.y;
                v = *(const float2*)(pb + H + j);     hpz.x += v.x; hpz.y += v.y;
                v = *(const float2*)(pb + 2 * H + j); hpn.x += v.x; hpn.y += v.y;
            }
            const float* bb = b_hh + (size_t)d * G3;
            float2 br = *(const float2*)(bb + j);
            float2 bz = *(const float2*)(bb + H + j);
            float2 bn = *(const float2*)(bb + 2 * H + j);
            const float* xr = xp + ((size_t)bo * T + te) * (2 * G3) + (size_t)d * G3;
            float2 xrv = *(const float2*)(xr + j);
            float2 xzv = *(const float2*)(xr + H + j);
            float2 xnv = *(const float2*)(xr + 2 * H + j);
            float rg0 = fast_sigmoid(xrv.x + hpr.x + br.x);
            float rg1 = fast_sigmoid(xrv.y + hpr.y + br.y);
            float zg0 = fast_sigmoid(xzv.x + hpz.x + bz.x);
            float zg1 = fast_sigmoid(xzv.y + hpz.y + bz.y);
            float ng0 = fast_tanh(xnv.x + rg0 * (hpn.x + bn.x));
            float ng1 = fast_tanh(xnv.y + rg1 * (hpn.y + bn.y));
            float2 hnew = make_float2((1.f - zg0) * ng0 + zg0 * hold.x,
                                      (1.f - zg1) * ng1 + zg1 * hold.y);
            *(float2*)&hbuf[((size_t)d * B + rr) * H + j] = hnew;
            uint32_t ph, pl;
            bfsplit2(hnew.x, hnew.y, ph, pl);
            hpk_hi[((size_t)d * B + rr) * H2 + (j >> 1)] = ph;
            hpk_lo[((size_t)d * B + rr) * H2 + (j >> 1)] = pl;
            *(float2*)&out[((size_t)bo * T + te) * (2 * H) + d * H + j] = hnew;
        }
        grid_sync(mybar, NCTAD, &gen);
    }
}

// ---------------- segment means ----------------
__global__ __launch_bounds__(256) void seg_mean_kernel(
    const float* __restrict__ vf, const float* __restrict__ loc,
    const int* __restrict__ v_len,
    float* __restrict__ lmean, float* __restrict__ rmean, float* __restrict__ cat)
{
    const int b = blockIdx.x;
    const int col = blockIdx.y * 256 + threadIdx.x;
    const int vl = v_len[b];
    const float scale = (float)(vl - 1);
    const float l0 = loc[b * 2], l1 = loc[b * 2 + 1];
    const int cond = (l0 <= l1);
    const float lhi = cond ? l0 : 0.f;
    const float rlo = cond ? l1 : 1.f;
    const int lend   = (int)floorf(lhi * scale);
    const int rstart = (int)floorf(rlo * scale);
    const int rend   = vl - 1;
    const int ok_l = (0 <= lend);
    const int ok_r = (rstart <= rend);

    float ls = 0.f, rs = 0.f, gs = 0.f;
    for (int t = 0; t < vl; t++) {
        float v = vf[((size_t)b * TV + t) * 1024 + col];
        gs += v;
        if (ok_l && t <= lend) ls += v;
        if (ok_r && t >= rstart) rs += v;
    }
    float lcnt = ok_l ? (float)(lend + 1) : 1.f;
    float rcnt = ok_r ? (float)(rend - rstart + 1) : 1.f;
    if (lcnt < 1.f) lcnt = 1.f;
    if (rcnt < 1.f) rcnt = 1.f;
    lmean[b * 1024 + col] = ls / lcnt;
    rmean[b * 1024 + col] = rs / rcnt;
    cat[(size_t)b * NCAT + 512 + col] = gs / (float)vl;
}

// ---------------- gather sen_fea ----------------
__global__ void gather_senfea(const float* __restrict__ words,
                              const int* __restrict__ lens,
                              float* __restrict__ out_sf, float* __restrict__ cat)
{
    const int b = blockIdx.x;
    const int t = lens[b] - 1;
    for (int c = threadIdx.x; c < 2 * SHID; c += blockDim.x) {
        float v = words[((size_t)b * TS + t) * (2 * SHID) + c];
        out_sf[(size_t)b * (2 * SHID) + c] = v;
        cat[(size_t)b * NCAT + c] = v;
    }
}

// ---------------- small GEMM with epilogue ----------------
__global__ __launch_bounds__(256) void gemm_small(
    const float* __restrict__ A, const float* __restrict__ W,
    const float* __restrict__ bias, const float* __restrict__ mul, int mulLd,
    float* __restrict__ C, int ldC, int M, int N, int K, int relu)
{
    const int n0 = blockIdx.x * 32, m0 = blockIdx.y * 32;
    __shared__ __align__(16) float As[32][34];
    __shared__ __align__(16) float Wsm[32][34];
    const int tid = threadIdx.x, ty = tid / 16, tx = tid % 16;
    float acc[2][2] = {{0.f, 0.f}, {0.f, 0.f}};

    for (int k0 = 0; k0 < K; k0 += 32) {
        for (int e = tid; e < 1024; e += 256) {
            int r = e / 32, k = e % 32;
            int kg = k0 + k;
            As[k][r]  = (kg < K) ? A[(size_t)(m0 + r) * K + kg] : 0.f;
            Wsm[k][r] = (kg < K) ? W[(size_t)(n0 + r) * K + kg] : 0.f;
        }
        __syncthreads();
#pragma unroll
        for (int k = 0; k < 32; k++) {
            float2 av = *(const float2*)&As[k][ty * 2];
            float2 wv = *(const float2*)&Wsm[k][tx * 2];
            acc[0][0] += av.x * wv.x;  acc[0][1] += av.x * wv.y;
            acc[1][0] += av.y * wv.x;  acc[1][1] += av.y * wv.y;
        }
        __syncthreads();
    }
#pragma unroll
    for (int i = 0; i < 2; i++) {
        int m = m0 + ty * 2 + i;
#pragma unroll
        for (int j = 0; j < 2; j++) {
            int n = n0 + tx * 2 + j;
            float v = acc[i][j] + bias[n];
            if (mul) v *= mul[(size_t)m * mulLd + n];
            if (relu) v = fmaxf(v, 0.f);
            C[(size_t)m * ldC + n] = v;
        }
    }
}

// ---------------- launch ----------------
extern "C" void kernel_launch(void* const* d_in, const int* in_sizes, int n_in,
                              void* d_out, int out_size)
{
    const float* gv     = (const float*)d_in[1];
    const float* sen    = (const float*)d_in[2];
    const float* loc    = (const float*)d_in[5];
    const int*   lens   = (const int*)  d_in[6];
    const int*   v_len  = (const int*)  d_in[7];
    const float* v_w_ih = (const float*)d_in[8];
    const float* v_w_hh = (const float*)d_in[9];
    const float* v_b_ih = (const float*)d_in[10];
    const float* v_b_hh = (const float*)d_in[11];
    const float* s_w_ih = (const float*)d_in[12];
    const float* s_w_hh = (const float*)d_in[13];
    const float* s_b_ih = (const float*)d_in[14];
    const float* s_b_hh = (const float*)d_in[15];
    const float* fc1_w  = (const float*)d_in[16];
    const float* fc1_b  = (const float*)d_in[17];
    const float* fc2_w  = (const float*)d_in[18];
    const float* fc2_b  = (const float*)d_in[19];
    const float* fc3_w  = (const float*)d_in[20];
    const float* fc3_b  = (const float*)d_in[21];
    const float* fc4_w  = (const float*)d_in[22];
    const float* fc4_b  = (const float*)d_in[23];

    float* out    = (float*)d_out;
    float* out_vf = out;
    float* out_sf = out + VF_ELEMS;
    float* out_ft = out + VF_ELEMS + SF_ELEMS;

    float *xp_v, *xp_s, *h_v, *h_s, *part_v, *part_s, *words;
    float *lmean, *rmean, *cat, *sproj;
    uint32_t *phv, *plv, *phs, *pls;
    int *perm_v, *lenp_v, *perm_s, *lenp_s, *cnt_v, *cnt_s;
    int *ridx_v, *ridx_s, *nv;
    unsigned* bar;
    cudaGetSymbolAddress((void**)&xp_v,   g_xp_v);
    cudaGetSymbolAddress((void**)&xp_s,   g_xp_s);
    cudaGetSymbolAddress((void**)&h_v,    g_h_v);
    cudaGetSymbolAddress((void**)&h_s,    g_h_s);
    cudaGetSymbolAddress((void**)&phv,    g_hpk_hi_v);
    cudaGetSymbolAddress((void**)&plv,    g_hpk_lo_v);
    cudaGetSymbolAddress((void**)&phs,    g_hpk_hi_s);
    cudaGetSymbolAddress((void**)&pls,    g_hpk_lo_s);
    cudaGetSymbolAddress((void**)&part_v, g_part_v);
    cudaGetSymbolAddress((void**)&part_s, g_part_s);
    cudaGetSymbolAddress((void**)&words,  g_words);
    cudaGetSymbolAddress((void**)&lmean,  g_lmean);
    cudaGetSymbolAddress((void**)&rmean,  g_rmean);
    cudaGetSymbolAddress((void**)&cat,    g_cat);
    cudaGetSymbolAddress((void**)&sproj,  g_sproj);
    cudaGetSymbolAddress((void**)&perm_v, g_perm_v);
    cudaGetSymbolAddress((void**)&lenp_v, g_lenp_v);
    cudaGetSymbolAddress((void**)&perm_s, g_perm_s);
    cudaGetSymbolAddress((void**)&lenp_s, g_lenp_s);
    cudaGetSymbolAddress((void**)&cnt_v,  g_cnt_v);
    cudaGetSymbolAddress((void**)&cnt_s,  g_cnt_s);
    cudaGetSymbolAddress((void**)&ridx_v, g_ridx_v);
    cudaGetSymbolAddress((void**)&ridx_s, g_ridx_s);
    cudaGetSymbolAddress((void**)&nv,     g_nv);
    cudaGetSymbolAddress((void**)&bar,    g_bar);

    const int GRU_SMEM = (2 * 4 * 96 * 12 + 2 * 4 * 128 * 12) * 4;
    cudaFuncSetAttribute(gru_persistent<512, 1536, 256, 16, 8, 64, 2>,
                         cudaFuncAttributeMaxDynamicSharedMemorySize, GRU_SMEM);
    cudaFuncSetAttribute(gru_persistent<256, 768, 40, 8, 4, 64, 2>,
                         cudaFuncAttributeMaxDynamicSharedMemorySize, GRU_SMEM);
    cudaFuncSetAttribute(gemm_bf16x3,
                         cudaFuncAttributeMaxDynamicSharedMemorySize, GEMM_SMEM);

    // 1. init
    sort_init_kernel<<<1, 128>>>(v_len, lens, perm_v, lenp_v, perm_s, lenp_s,
                                 cnt_v, cnt_s, ridx_v, ridx_s, nv, bar);
    zero_h_kernel<<<(2*B*VHID + 255) / 256, 256>>>(h_v, h_s, phv, plv, phs, pls);
    zero_out_kernel<<<(int)(VF_ELEMS/4 + 255) / 256, 256>>>((float4*)out_vf,
                                                            (int)(VF_ELEMS/4));

    // 2. input projections (3xBF16, row-compacted)
    gemm_bf16x3<<<dim3(3072/128, (B*TV)/128), 256, GEMM_SMEM>>>(
        gv,  v_w_ih, v_b_ih, xp_v, ridx_v, nv,     3072, VIN);
    gemm_bf16x3<<<dim3(1536/128, (B*TS)/128), 256, GEMM_SMEM>>>(
        sen, s_w_ih, s_b_ih, xp_s, ridx_s, nv + 1, 1536, SIN);

    // 3. persistent visual GRU (per-direction barriers)
    gru_persistent<512, 1536, 256, 16, 8, 64, 2><<<256, 256, GRU_SMEM>>>(
        xp_v, v_w_hh, v_b_hh, h_v, phv, plv, part_v, out_vf,
        perm_v, lenp_v, cnt_v, bar);

    // 4. persistent sentence GRU (per-direction barriers)
    gru_persistent<256, 768, 40, 8, 4, 64, 2><<<64, 256, GRU_SMEM>>>(
        xp_s, s_w_hh, s_b_hh, h_s, phs, pls, part_s, words,
        perm_s, lenp_s, cnt_s, bar + 4);

    // 5. sen_fea gather
    gather_senfea<<<B, 256>>>(words, lens, out_sf, cat);

    // 6. segment means + global mean
    seg_mean_kernel<<<dim3(B, 4), 256>>>(out_vf, loc, v_len, lmean, rmean, cat);

    // 7. FC stack
    gemm_small<<<dim3(LCROSS/32, B/32), 256>>>(out_sf, fc2_w, fc2_b, nullptr, 0,
                                               sproj, LCROSS, B, LCROSS, 2*SHID, 0);
    gemm_small<<<dim3(LCROSS/32, B/32), 256>>>(lmean, fc1_w, fc1_b, sproj, LCROSS,
                                               cat + 1536, NCAT, B, LCROSS, 2*VHID, 1);
    gemm_small<<<dim3(LCROSS/32, B/32), 256>>>(rmean, fc1_w, fc1_b, sproj, LCROSS,
                                               cat + 2048, NCAT, B, LCROSS, 2*VHID, 1);
    gemm_small<<<dim3(NLOC/32, B/32), 256>>>(loc, fc3_w, fc3_b, nullptr, 0,
                                             cat + 2560, NCAT, B, NLOC, 2, 1);
    gemm_small<<<dim3(NFEAT/32, B/32), 256>>>(cat, fc4_w, fc4_b, nullptr, 0,
                                              out_ft, NFEAT, B, NFEAT, NCAT, 1);
}